// round 1
// baseline (speedup 1.0000x reference)
#include <cuda_runtime.h>
#include <math.h>

#define B_  4
#define T_  2048
#define C_  1024
#define H_  16
#define HD_ 64
#define M_  (B_*T_)   // 8192

// Scratch (allocation-free: __device__ globals)
__device__ float g_q[B_*H_*T_*HD_];
__device__ float g_k[B_*H_*T_*HD_];
__device__ float g_v[B_*H_*T_*HD_];
__device__ float g_att[B_*T_*C_];   // attention output in [B,H,T,hd] layout

// ---------------------------------------------------------------------------
// Kernel 1: fused QKV projection.
//  q/k/v[b,h,t,d] = sum_c x[b,t,c] * W{q,k,v}[h,c,d] + b{q,k,v}[h,d]
//  Tiled SGEMM: BM=64, BN=64 (= hd), BK=16. grid=(M/64, 3*H). 256 thr, 4x4 uT.
// ---------------------------------------------------------------------------
__global__ __launch_bounds__(256) void qkv_kernel(
    const float* __restrict__ x,
    const float* __restrict__ Wq, const float* __restrict__ bq,
    const float* __restrict__ Wk, const float* __restrict__ bk,
    const float* __restrict__ Wv, const float* __restrict__ bv)
{
    __shared__ float As[16][65];   // [k][m], padded
    __shared__ float Bs[16][64];   // [k][n]

    int tid = threadIdx.x;
    int tx = tid & 15, ty = tid >> 4;
    int mt = blockIdx.x;
    int nt = blockIdx.y;
    int which = nt >> 4, h = nt & 15;

    const float* W; const float* bias; float* out;
    if (which == 0)      { W = Wq; bias = bq; out = g_q; }
    else if (which == 1) { W = Wk; bias = bk; out = g_k; }
    else                 { W = Wv; bias = bv; out = g_v; }
    const float* Wh = W + (size_t)h * C_ * HD_;

    int ar = tid >> 2;          // 0..63  (A row)
    int ac = (tid & 3) << 2;    // 0,4,8,12 (A col group)
    int br = tid >> 4;          // 0..15  (B row)
    int bc = (tid & 15) << 2;   // 0..60  (B col group)

    float acc[4][4] = {};
    const float* Arow = x + (size_t)(mt*64 + ar) * C_;

    for (int k0 = 0; k0 < C_; k0 += 16) {
        float4 a4 = *(const float4*)(Arow + k0 + ac);
        As[ac+0][ar] = a4.x; As[ac+1][ar] = a4.y;
        As[ac+2][ar] = a4.z; As[ac+3][ar] = a4.w;
        float4 b4 = *(const float4*)(Wh + (size_t)(k0+br)*HD_ + bc);
        *(float4*)&Bs[br][bc] = b4;
        __syncthreads();
        #pragma unroll
        for (int kk = 0; kk < 16; kk++) {
            float4 bb = *(float4*)&Bs[kk][tx<<2];
            float b0=bb.x, b1=bb.y, b2=bb.z, b3=bb.w;
            float a[4];
            #pragma unroll
            for (int i = 0; i < 4; i++) a[i] = As[kk][(ty<<2)+i];
            #pragma unroll
            for (int i = 0; i < 4; i++) {
                acc[i][0] += a[i]*b0; acc[i][1] += a[i]*b1;
                acc[i][2] += a[i]*b2; acc[i][3] += a[i]*b3;
            }
        }
        __syncthreads();
    }

    int d = tx << 2;
    #pragma unroll
    for (int i = 0; i < 4; i++) {
        int m = mt*64 + (ty<<2) + i;
        int b_ = m >> 11, t = m & (T_-1);
        float4 o;
        o.x = acc[i][0] + bias[h*HD_ + d+0];
        o.y = acc[i][1] + bias[h*HD_ + d+1];
        o.z = acc[i][2] + bias[h*HD_ + d+2];
        o.w = acc[i][3] + bias[h*HD_ + d+3];
        *(float4*)&out[(((size_t)(b_*H_ + h))*T_ + t)*HD_ + d] = o;
    }
}

// ---------------------------------------------------------------------------
// Kernel 2: causal flash attention per (b,h, 64-row q tile).
//  scale = C^-0.5 = 1/32 (faithful quirk). Online softmax, shuffle reductions.
// ---------------------------------------------------------------------------
__global__ __launch_bounds__(256) void attn_kernel()
{
    extern __shared__ float sm[];
    float* Qs = sm;            // [64][64] row-major
    float* Kt = sm + 4096;     // [d][r]  (K transposed)
    float* Vs = sm + 8192;     // [s][d]
    float* Ps = sm + 12288;    // [r][s]

    int tid = threadIdx.x;
    int tx = tid & 15, ty = tid >> 4;
    int qt = blockIdx.x, bh = blockIdx.y;

    const float* Qg = g_q + (size_t)bh * T_ * HD_;
    const float* Kg = g_k + (size_t)bh * T_ * HD_;
    const float* Vg = g_v + (size_t)bh * T_ * HD_;

    int lr = tid >> 2;          // 0..63 row
    int lc = (tid & 3) << 4;    // 0,16,32,48 col base (16 floats per thread)

    #pragma unroll
    for (int u = 0; u < 4; u++) {
        float4 q4 = *(const float4*)(Qg + (size_t)(qt*64 + lr)*HD_ + lc + u*4);
        *(float4*)&Qs[lr*64 + lc + u*4] = q4;
    }

    const float NEG = -1e30f;
    float m_i[4] = {NEG, NEG, NEG, NEG};
    float l_i[4] = {0.f, 0.f, 0.f, 0.f};
    float acc[4][4] = {};
    const float scale = 0.03125f;  // 1024^-0.5

    for (int j0 = 0; j0 <= qt; j0++) {
        // Load K (transposed) and V tiles
        #pragma unroll
        for (int u = 0; u < 4; u++) {
            int c = lc + u*4;
            float4 k4 = *(const float4*)(Kg + (size_t)(j0*64 + lr)*HD_ + c);
            Kt[(c+0)*64 + lr] = k4.x; Kt[(c+1)*64 + lr] = k4.y;
            Kt[(c+2)*64 + lr] = k4.z; Kt[(c+3)*64 + lr] = k4.w;
            float4 v4 = *(const float4*)(Vg + (size_t)(j0*64 + lr)*HD_ + c);
            *(float4*)&Vs[lr*64 + c] = v4;
        }
        __syncthreads();

        // S = Q K^T (4x4 per thread)
        float s[4][4] = {};
        #pragma unroll 4
        for (int dd = 0; dd < 64; dd++) {
            float4 kk4 = *(float4*)&Kt[dd*64 + (tx<<2)];
            float b0=kk4.x, b1=kk4.y, b2=kk4.z, b3=kk4.w;
            #pragma unroll
            for (int i = 0; i < 4; i++) {
                float a = Qs[((ty<<2)+i)*64 + dd];
                s[i][0] += a*b0; s[i][1] += a*b1;
                s[i][2] += a*b2; s[i][3] += a*b3;
            }
        }

        int qi_base = qt*64 + (ty<<2);
        int kj_base = j0*64 + (tx<<2);
        bool diag = (j0 == qt);
        #pragma unroll
        for (int i = 0; i < 4; i++) {
            #pragma unroll
            for (int j = 0; j < 4; j++) {
                float v = s[i][j] * scale;
                if (diag && (kj_base + j > qi_base + i)) v = NEG;
                s[i][j] = v;
            }
        }

        // online softmax per row (row spread over tx half-warp group, width 16)
        #pragma unroll
        for (int i = 0; i < 4; i++) {
            float mx = fmaxf(fmaxf(s[i][0], s[i][1]), fmaxf(s[i][2], s[i][3]));
            #pragma unroll
            for (int off = 8; off >= 1; off >>= 1)
                mx = fmaxf(mx, __shfl_xor_sync(0xffffffffu, mx, off, 16));
            float m_new = fmaxf(m_i[i], mx);
            float alpha = __expf(m_i[i] - m_new);
            m_i[i] = m_new;
            float rs = 0.f;
            #pragma unroll
            for (int j = 0; j < 4; j++) {
                float p = __expf(s[i][j] - m_new);
                Ps[((ty<<2)+i)*64 + (tx<<2) + j] = p;
                rs += p;
            }
            #pragma unroll
            for (int off = 8; off >= 1; off >>= 1)
                rs += __shfl_xor_sync(0xffffffffu, rs, off, 16);
            l_i[i] = l_i[i]*alpha + rs;
            acc[i][0] *= alpha; acc[i][1] *= alpha;
            acc[i][2] *= alpha; acc[i][3] *= alpha;
        }
        __syncthreads();

        // O += P V
        #pragma unroll 4
        for (int ss = 0; ss < 64; ss++) {
            float4 vv = *(float4*)&Vs[ss*64 + (tx<<2)];
            #pragma unroll
            for (int i = 0; i < 4; i++) {
                float p = Ps[((ty<<2)+i)*64 + ss];
                acc[i][0] += p*vv.x; acc[i][1] += p*vv.y;
                acc[i][2] += p*vv.z; acc[i][3] += p*vv.w;
            }
        }
        __syncthreads();
    }

    float* Og = g_att + (size_t)bh * T_ * HD_;
    #pragma unroll
    for (int i = 0; i < 4; i++) {
        float inv = 1.0f / l_i[i];
        float4 o;
        o.x = acc[i][0]*inv; o.y = acc[i][1]*inv;
        o.z = acc[i][2]*inv; o.w = acc[i][3]*inv;
        *(float4*)&Og[(size_t)(qt*64 + (ty<<2)+i)*HD_ + (tx<<2)] = o;
    }
}

// ---------------------------------------------------------------------------
// Kernel 3: output projection with head-concat remap folded into A load.
//  out[b,t,n] = sum_k att[b, k/64 (head), t, k%64] * Wp[k,n] + bp[n]
// ---------------------------------------------------------------------------
__global__ __launch_bounds__(256) void proj_kernel(
    const float* __restrict__ Wp, const float* __restrict__ bp,
    float* __restrict__ out)
{
    __shared__ float As[16][65];
    __shared__ float Bs[16][64];

    int tid = threadIdx.x;
    int tx = tid & 15, ty = tid >> 4;
    int mt = blockIdx.x;
    int nt = blockIdx.y;

    int ar = tid >> 2;
    int ac = (tid & 3) << 2;
    int br = tid >> 4;
    int bc = (tid & 15) << 2;

    int m = mt*64 + ar;
    int b_ = m >> 11, t = m & (T_-1);

    float acc[4][4] = {};

    for (int k0 = 0; k0 < C_; k0 += 16) {
        int k = k0 + ac;
        int h = k >> 6, dlo = k & 63;
        float4 a4 = *(const float4*)(g_att +
            (((size_t)(b_*H_ + h))*T_ + t)*HD_ + dlo);
        As[ac+0][ar] = a4.x; As[ac+1][ar] = a4.y;
        As[ac+2][ar] = a4.z; As[ac+3][ar] = a4.w;
        float4 b4 = *(const float4*)(Wp + (size_t)(k0+br)*C_ + nt*64 + bc);
        *(float4*)&Bs[br][bc] = b4;
        __syncthreads();
        #pragma unroll
        for (int kk = 0; kk < 16; kk++) {
            float4 bb = *(float4*)&Bs[kk][tx<<2];
            float b0=bb.x, b1=bb.y, b2=bb.z, b3=bb.w;
            float a[4];
            #pragma unroll
            for (int i = 0; i < 4; i++) a[i] = As[kk][(ty<<2)+i];
            #pragma unroll
            for (int i = 0; i < 4; i++) {
                acc[i][0] += a[i]*b0; acc[i][1] += a[i]*b1;
                acc[i][2] += a[i]*b2; acc[i][3] += a[i]*b3;
            }
        }
        __syncthreads();
    }

    int d = tx << 2;
    #pragma unroll
    for (int i = 0; i < 4; i++) {
        int m2 = mt*64 + (ty<<2) + i;
        float4 o;
        o.x = acc[i][0] + bp[nt*64 + d+0];
        o.y = acc[i][1] + bp[nt*64 + d+1];
        o.z = acc[i][2] + bp[nt*64 + d+2];
        o.w = acc[i][3] + bp[nt*64 + d+3];
        *(float4*)&out[(size_t)m2*C_ + nt*64 + d] = o;
    }
}

// ---------------------------------------------------------------------------
extern "C" void kernel_launch(void* const* d_in, const int* in_sizes, int n_in,
                              void* d_out, int out_size)
{
    const float* x  = (const float*)d_in[0];
    const float* Wq = (const float*)d_in[1];
    const float* bq = (const float*)d_in[2];
    const float* Wk = (const float*)d_in[3];
    const float* bk = (const float*)d_in[4];
    const float* Wv = (const float*)d_in[5];
    const float* bv = (const float*)d_in[6];
    const float* Wp = (const float*)d_in[7];
    const float* bp = (const float*)d_in[8];
    float* out = (float*)d_out;

    cudaFuncSetAttribute(attn_kernel,
        cudaFuncAttributeMaxDynamicSharedMemorySize, 65536);

    qkv_kernel<<<dim3(128, 48), 256>>>(x, Wq, bq, Wk, bk, Wv, bv);
    attn_kernel<<<dim3(32, 64), 256, 65536>>>();
    proj_kernel<<<dim3(128, 16), 256>>>(Wp, bp, out);
}

// round 3
// speedup vs baseline: 1.4917x; 1.4917x over previous
#include <cuda_runtime.h>
#include <cuda_bf16.h>
#include <math.h>
#include <stdint.h>

#define B_  4
#define T_  2048
#define C_  1024
#define H_  16
#define HD_ 64
#define M_  (B_*T_)   // 8192

// Scratch (allocation-free: __device__ globals)
__device__ float g_q[B_*H_*T_*HD_];
__device__ float g_k[B_*H_*T_*HD_];
__device__ float g_v[B_*H_*T_*HD_];
__device__ float g_att[B_*T_*C_];

// ---------------------------------------------------------------------------
// Warp-level tensor-core helpers (mma.sync path — portable to sm_100 baseline)
// ---------------------------------------------------------------------------
__device__ __forceinline__ uint32_t smem_u32(const void* p){
    uint32_t a;
    asm("{ .reg .u64 t; cvta.to.shared.u64 t, %1; cvt.u32.u64 %0, t; }"
        : "=r"(a) : "l"(p));
    return a;
}
__device__ __forceinline__ void ldsm_x4(uint32_t* r, uint32_t addr){
    asm volatile("ldmatrix.sync.aligned.m8n8.x4.shared.b16 {%0,%1,%2,%3}, [%4];"
        : "=r"(r[0]), "=r"(r[1]), "=r"(r[2]), "=r"(r[3]) : "r"(addr));
}
__device__ __forceinline__ void ldsm_x2(uint32_t* r, uint32_t addr){
    asm volatile("ldmatrix.sync.aligned.m8n8.x2.shared.b16 {%0,%1}, [%2];"
        : "=r"(r[0]), "=r"(r[1]) : "r"(addr));
}
__device__ __forceinline__ void mma16816(float* c, const uint32_t* a, const uint32_t* b){
    asm volatile(
        "mma.sync.aligned.m16n8k16.row.col.f32.bf16.bf16.f32 "
        "{%0,%1,%2,%3}, {%4,%5,%6,%7}, {%8,%9}, {%0,%1,%2,%3};"
        : "+f"(c[0]), "+f"(c[1]), "+f"(c[2]), "+f"(c[3])
        : "r"(a[0]), "r"(a[1]), "r"(a[2]), "r"(a[3]), "r"(b[0]), "r"(b[1]));
}

__device__ __forceinline__ void split_pack(float4 a, uint2& hi, uint2& lo){
    __nv_bfloat16 h0 = __float2bfloat16(a.x), h1 = __float2bfloat16(a.y);
    __nv_bfloat16 h2 = __float2bfloat16(a.z), h3 = __float2bfloat16(a.w);
    __nv_bfloat16 l0 = __float2bfloat16(a.x - __bfloat162float(h0));
    __nv_bfloat16 l1 = __float2bfloat16(a.y - __bfloat162float(h1));
    __nv_bfloat16 l2 = __float2bfloat16(a.z - __bfloat162float(h2));
    __nv_bfloat16 l3 = __float2bfloat16(a.w - __bfloat162float(h3));
    __nv_bfloat162 hp0(h0, h1), hp1(h2, h3), lp0(l0, l1), lp1(l2, l3);
    hi.x = *(uint32_t*)&hp0; hi.y = *(uint32_t*)&hp1;
    lo.x = *(uint32_t*)&lp0; lo.y = *(uint32_t*)&lp1;
}

#define BK  32
#define SK  40   // padded k-stride in bf16 elems (80B: conflict-free ldmatrix)

// ---------------------------------------------------------------------------
// GEMM core: 128x128 CTA tile, BK=32, 8 warps (2m x 4n), bf16 3-pass split.
// ---------------------------------------------------------------------------
struct GemmSmem {
    __nv_bfloat16 Ah[128*SK];
    __nv_bfloat16 Al[128*SK];
    __nv_bfloat16 Bh[128*SK];
    __nv_bfloat16 Bl[128*SK];
};

__device__ __forceinline__ void gemm_mma_chunk(
    uint32_t sAh, uint32_t sAl, uint32_t sBh, uint32_t sBl,
    uint32_t aoff, uint32_t boff, float acc[4][4][4])
{
    #pragma unroll
    for (int pass = 0; pass < 3; pass++) {
        uint32_t sA = (pass == 2) ? sAl : sAh;
        uint32_t sB = (pass == 1) ? sBl : sBh;
        #pragma unroll
        for (int ks = 0; ks < 2; ks++) {
            uint32_t af[4][4], bf[4][2];
            #pragma unroll
            for (int mt = 0; mt < 4; mt++)
                ldsm_x4(af[mt], sA + aoff + (mt*16*SK + ks*16)*2);
            #pragma unroll
            for (int nt = 0; nt < 4; nt++)
                ldsm_x2(bf[nt], sB + boff + (nt*8*SK + ks*16)*2);
            #pragma unroll
            for (int mt = 0; mt < 4; mt++)
                #pragma unroll
                for (int nt = 0; nt < 4; nt++)
                    mma16816(acc[mt][nt], af[mt], bf[nt]);
        }
    }
}

// ---------------------------------------------------------------------------
// Kernel 1: QKV projection.  grid=(64, 24): nt>>3 selects q/k/v, 2 heads/CTA.
// ---------------------------------------------------------------------------
__global__ __launch_bounds__(256) void qkv_mma(
    const float* __restrict__ x,
    const float* __restrict__ Wq, const float* __restrict__ bq,
    const float* __restrict__ Wk, const float* __restrict__ bk,
    const float* __restrict__ Wv, const float* __restrict__ bv)
{
    __shared__ GemmSmem sm;
    int tid = threadIdx.x, wid = tid >> 5, lane = tid & 31;
    int wm = wid >> 2, wn = wid & 3;
    int mt_ = blockIdx.x, nt_ = blockIdx.y;
    int which = nt_ >> 3, hbase = (nt_ & 7) * 2;
    const int m0 = mt_ * 128;

    const float* W; const float* bias; float* out;
    if (which == 0)      { W = Wq; bias = bq; out = g_q; }
    else if (which == 1) { W = Wk; bias = bk; out = g_k; }
    else                 { W = Wv; bias = bv; out = g_v; }

    uint32_t sAh = smem_u32(sm.Ah), sAl = smem_u32(sm.Al);
    uint32_t sBh = smem_u32(sm.Bh), sBl = smem_u32(sm.Bl);

    // per-warp ldmatrix lane addressing offsets (in elements, then bytes)
    uint32_t aoff = ((wm*64 + (lane & 15)) * SK + ((lane >> 4) << 3)) * 2;
    uint32_t boff = ((wn*32 + (lane & 7)) * SK + (((lane >> 3) & 1) << 3)) * 2;

    float acc[4][4][4] = {};

    for (int k0 = 0; k0 < C_; k0 += BK) {
        // A tile fill: x[m0..+128, k0..+32]
        #pragma unroll
        for (int it = 0; it < 4; it++) {
            int g = tid + it*256;
            int r = g >> 3, kb = (g & 7) << 2;
            float4 a = *(const float4*)(x + (size_t)(m0 + r) * C_ + k0 + kb);
            uint2 hi, lo; split_pack(a, hi, lo);
            *(uint2*)&sm.Ah[r*SK + kb] = hi;
            *(uint2*)&sm.Al[r*SK + kb] = lo;
        }
        // B tile fill: W[h, k, d] -> sB[n=d+(h-hbase)*64][k]
        #pragma unroll
        for (int it = 0; it < 4; it++) {
            int g = tid + it*256;
            int n = g & 127, k4 = (g >> 7) << 2;
            int h = hbase + (n >> 6), d = n & 63;
            const float* wp = W + (size_t)h * C_ * HD_ + (size_t)(k0 + k4) * HD_ + d;
            float4 a = make_float4(wp[0], wp[HD_], wp[2*HD_], wp[3*HD_]);
            uint2 hi, lo; split_pack(a, hi, lo);
            *(uint2*)&sm.Bh[n*SK + k4] = hi;
            *(uint2*)&sm.Bl[n*SK + k4] = lo;
        }
        __syncthreads();
        gemm_mma_chunk(sAh, sAl, sBh, sBl, aoff, boff, acc);
        __syncthreads();
    }

    // epilogue
    #pragma unroll
    for (int mt = 0; mt < 4; mt++) {
        int mrow = m0 + wm*64 + mt*16 + (lane >> 2);
        #pragma unroll
        for (int half = 0; half < 2; half++) {
            int m = mrow + half*8;
            int b_ = m >> 11, t = m & (T_-1);
            #pragma unroll
            for (int nt = 0; nt < 4; nt++) {
                int n = wn*32 + nt*8 + ((lane & 3) << 1);
                int h = hbase + (n >> 6), d = n & 63;
                float c0 = acc[mt][nt][half*2+0] + bias[h*HD_ + d];
                float c1 = acc[mt][nt][half*2+1] + bias[h*HD_ + d + 1];
                float2 o = make_float2(c0, c1);
                *(float2*)&out[(((size_t)(b_*H_ + h))*T_ + t)*HD_ + d] = o;
            }
        }
    }
}

// ---------------------------------------------------------------------------
// Kernel 2: causal flash attention per (b,h, 64-row q tile). fp32 SIMT.
// ---------------------------------------------------------------------------
__global__ __launch_bounds__(256) void attn_kernel()
{
    extern __shared__ float smf[];
    float* Qs = smf;
    float* Kt = smf + 4096;
    float* Vs = smf + 8192;
    float* Ps = smf + 12288;

    int tid = threadIdx.x;
    int tx = tid & 15, ty = tid >> 4;
    int qt = blockIdx.x, bh = blockIdx.y;

    const float* Qg = g_q + (size_t)bh * T_ * HD_;
    const float* Kg = g_k + (size_t)bh * T_ * HD_;
    const float* Vg = g_v + (size_t)bh * T_ * HD_;

    int lr = tid >> 2;
    int lc = (tid & 3) << 4;

    #pragma unroll
    for (int u = 0; u < 4; u++) {
        float4 q4 = *(const float4*)(Qg + (size_t)(qt*64 + lr)*HD_ + lc + u*4);
        *(float4*)&Qs[lr*64 + lc + u*4] = q4;
    }

    const float NEG = -1e30f;
    float m_i[4] = {NEG, NEG, NEG, NEG};
    float l_i[4] = {0.f, 0.f, 0.f, 0.f};
    float acc[4][4] = {};
    const float scale = 0.03125f;

    for (int j0 = 0; j0 <= qt; j0++) {
        #pragma unroll
        for (int u = 0; u < 4; u++) {
            int c = lc + u*4;
            float4 k4 = *(const float4*)(Kg + (size_t)(j0*64 + lr)*HD_ + c);
            Kt[(c+0)*64 + lr] = k4.x; Kt[(c+1)*64 + lr] = k4.y;
            Kt[(c+2)*64 + lr] = k4.z; Kt[(c+3)*64 + lr] = k4.w;
            float4 v4 = *(const float4*)(Vg + (size_t)(j0*64 + lr)*HD_ + c);
            *(float4*)&Vs[lr*64 + c] = v4;
        }
        __syncthreads();

        float s[4][4] = {};
        #pragma unroll 4
        for (int dd = 0; dd < 64; dd++) {
            float4 kk4 = *(float4*)&Kt[dd*64 + (tx<<2)];
            float b0=kk4.x, b1=kk4.y, b2=kk4.z, b3=kk4.w;
            #pragma unroll
            for (int i = 0; i < 4; i++) {
                float a = Qs[((ty<<2)+i)*64 + dd];
                s[i][0] += a*b0; s[i][1] += a*b1;
                s[i][2] += a*b2; s[i][3] += a*b3;
            }
        }

        int qi_base = qt*64 + (ty<<2);
        int kj_base = j0*64 + (tx<<2);
        bool diag = (j0 == qt);
        #pragma unroll
        for (int i = 0; i < 4; i++) {
            #pragma unroll
            for (int j = 0; j < 4; j++) {
                float v = s[i][j] * scale;
                if (diag && (kj_base + j > qi_base + i)) v = NEG;
                s[i][j] = v;
            }
        }

        #pragma unroll
        for (int i = 0; i < 4; i++) {
            float mx = fmaxf(fmaxf(s[i][0], s[i][1]), fmaxf(s[i][2], s[i][3]));
            #pragma unroll
            for (int off = 8; off >= 1; off >>= 1)
                mx = fmaxf(mx, __shfl_xor_sync(0xffffffffu, mx, off, 16));
            float m_new = fmaxf(m_i[i], mx);
            float alpha = __expf(m_i[i] - m_new);
            m_i[i] = m_new;
            float rs = 0.f;
            #pragma unroll
            for (int j = 0; j < 4; j++) {
                float p = __expf(s[i][j] - m_new);
                Ps[((ty<<2)+i)*64 + (tx<<2) + j] = p;
                rs += p;
            }
            #pragma unroll
            for (int off = 8; off >= 1; off >>= 1)
                rs += __shfl_xor_sync(0xffffffffu, rs, off, 16);
            l_i[i] = l_i[i]*alpha + rs;
            acc[i][0] *= alpha; acc[i][1] *= alpha;
            acc[i][2] *= alpha; acc[i][3] *= alpha;
        }
        __syncthreads();

        #pragma unroll 4
        for (int ss = 0; ss < 64; ss++) {
            float4 vv = *(float4*)&Vs[ss*64 + (tx<<2)];
            #pragma unroll
            for (int i = 0; i < 4; i++) {
                float p = Ps[((ty<<2)+i)*64 + ss];
                acc[i][0] += p*vv.x; acc[i][1] += p*vv.y;
                acc[i][2] += p*vv.z; acc[i][3] += p*vv.w;
            }
        }
        __syncthreads();
    }

    float* Og = g_att + (size_t)bh * T_ * HD_;
    #pragma unroll
    for (int i = 0; i < 4; i++) {
        float inv = 1.0f / l_i[i];
        float4 o;
        o.x = acc[i][0]*inv; o.y = acc[i][1]*inv;
        o.z = acc[i][2]*inv; o.w = acc[i][3]*inv;
        *(float4*)&Og[(size_t)(qt*64 + (ty<<2)+i)*HD_ + (tx<<2)] = o;
    }
}

// ---------------------------------------------------------------------------
// Kernel 3: output projection.  grid=(64, 8). Head-concat remap in A fill.
// ---------------------------------------------------------------------------
__global__ __launch_bounds__(256) void proj_mma(
    const float* __restrict__ Wp, const float* __restrict__ bp,
    float* __restrict__ outp)
{
    __shared__ GemmSmem sm;
    int tid = threadIdx.x, wid = tid >> 5, lane = tid & 31;
    int wm = wid >> 2, wn = wid & 3;
    const int m0 = blockIdx.x * 128, n0 = blockIdx.y * 128;

    uint32_t sAh = smem_u32(sm.Ah), sAl = smem_u32(sm.Al);
    uint32_t sBh = smem_u32(sm.Bh), sBl = smem_u32(sm.Bl);
    uint32_t aoff = ((wm*64 + (lane & 15)) * SK + ((lane >> 4) << 3)) * 2;
    uint32_t boff = ((wn*32 + (lane & 7)) * SK + (((lane >> 3) & 1) << 3)) * 2;

    float acc[4][4][4] = {};

    for (int k0 = 0; k0 < C_; k0 += BK) {
        #pragma unroll
        for (int it = 0; it < 4; it++) {
            int g = tid + it*256;
            int r = g >> 3, kb = (g & 7) << 2;
            int m = m0 + r;
            int b_ = m >> 11, t = m & (T_-1);
            int k = k0 + kb, h = k >> 6, dl = k & 63;
            float4 a = *(const float4*)(g_att +
                (((size_t)(b_*H_ + h))*T_ + t)*HD_ + dl);
            uint2 hi, lo; split_pack(a, hi, lo);
            *(uint2*)&sm.Ah[r*SK + kb] = hi;
            *(uint2*)&sm.Al[r*SK + kb] = lo;
        }
        #pragma unroll
        for (int it = 0; it < 4; it++) {
            int g = tid + it*256;
            int n = g & 127, k4 = (g >> 7) << 2;
            const float* wp = Wp + (size_t)(k0 + k4) * C_ + n0 + n;
            float4 a = make_float4(wp[0], wp[C_], wp[2*C_], wp[3*C_]);
            uint2 hi, lo; split_pack(a, hi, lo);
            *(uint2*)&sm.Bh[n*SK + k4] = hi;
            *(uint2*)&sm.Bl[n*SK + k4] = lo;
        }
        __syncthreads();
        gemm_mma_chunk(sAh, sAl, sBh, sBl, aoff, boff, acc);
        __syncthreads();
    }

    #pragma unroll
    for (int mt = 0; mt < 4; mt++) {
        int mrow = m0 + wm*64 + mt*16 + (lane >> 2);
        #pragma unroll
        for (int half = 0; half < 2; half++) {
            int m = mrow + half*8;
            #pragma unroll
            for (int nt = 0; nt < 4; nt++) {
                int n = wn*32 + nt*8 + ((lane & 3) << 1);
                float c0 = acc[mt][nt][half*2+0] + bp[n0 + n];
                float c1 = acc[mt][nt][half*2+1] + bp[n0 + n + 1];
                *(float2*)&outp[(size_t)m*C_ + n0 + n] = make_float2(c0, c1);
            }
        }
    }
}

// ---------------------------------------------------------------------------
extern "C" void kernel_launch(void* const* d_in, const int* in_sizes, int n_in,
                              void* d_out, int out_size)
{
    const float* x  = (const float*)d_in[0];
    const float* Wq = (const float*)d_in[1];
    const float* bq = (const float*)d_in[2];
    const float* Wk = (const float*)d_in[3];
    const float* bk = (const float*)d_in[4];
    const float* Wv = (const float*)d_in[5];
    const float* bv = (const float*)d_in[6];
    const float* Wp = (const float*)d_in[7];
    const float* bp = (const float*)d_in[8];
    float* out = (float*)d_out;

    cudaFuncSetAttribute(attn_kernel, cudaFuncAttributeMaxDynamicSharedMemorySize, 65536);

    qkv_mma<<<dim3(64, 24), 256>>>(x, Wq, bq, Wk, bk, Wv, bv);
    attn_kernel<<<dim3(32, 64), 256, 65536>>>();
    proj_mma<<<dim3(64, 8), 256>>>(Wp, bp, out);
}

// round 5
// speedup vs baseline: 2.5274x; 1.6943x over previous
#include <cuda_runtime.h>
#include <cuda_bf16.h>
#include <math.h>
#include <stdint.h>

#define B_  4
#define T_  2048
#define C_  1024
#define H_  16
#define HD_ 64
#define M_  (B_*T_)   // 8192

// Scratch (allocation-free: __device__ globals)
__device__ float g_q[B_*H_*T_*HD_];
__device__ float g_k[B_*H_*T_*HD_];
__device__ float g_v[B_*H_*T_*HD_];
__device__ float g_att[B_*T_*C_];

// ---------------------------------------------------------------------------
// mma.sync helpers (portable HMMA path, works on plain sm_100 target)
// ---------------------------------------------------------------------------
__device__ __forceinline__ uint32_t smem_u32(const void* p){
    uint32_t a;
    asm("{ .reg .u64 t; cvta.to.shared.u64 t, %1; cvt.u32.u64 %0, t; }"
        : "=r"(a) : "l"(p));
    return a;
}
__device__ __forceinline__ void ldsm_x4(uint32_t* r, uint32_t addr){
    asm volatile("ldmatrix.sync.aligned.m8n8.x4.shared.b16 {%0,%1,%2,%3}, [%4];"
        : "=r"(r[0]), "=r"(r[1]), "=r"(r[2]), "=r"(r[3]) : "r"(addr));
}
__device__ __forceinline__ void ldsm_x2(uint32_t* r, uint32_t addr){
    asm volatile("ldmatrix.sync.aligned.m8n8.x2.shared.b16 {%0,%1}, [%2];"
        : "=r"(r[0]), "=r"(r[1]) : "r"(addr));
}
__device__ __forceinline__ void mma16816(float* c, const uint32_t* a, const uint32_t* b){
    asm volatile(
        "mma.sync.aligned.m16n8k16.row.col.f32.bf16.bf16.f32 "
        "{%0,%1,%2,%3}, {%4,%5,%6,%7}, {%8,%9}, {%0,%1,%2,%3};"
        : "+f"(c[0]), "+f"(c[1]), "+f"(c[2]), "+f"(c[3])
        : "r"(a[0]), "r"(a[1]), "r"(a[2]), "r"(a[3]), "r"(b[0]), "r"(b[1]));
}

__device__ __forceinline__ void split_pack(float4 a, uint2& hi, uint2& lo){
    __nv_bfloat16 h0 = __float2bfloat16(a.x), h1 = __float2bfloat16(a.y);
    __nv_bfloat16 h2 = __float2bfloat16(a.z), h3 = __float2bfloat16(a.w);
    __nv_bfloat16 l0 = __float2bfloat16(a.x - __bfloat162float(h0));
    __nv_bfloat16 l1 = __float2bfloat16(a.y - __bfloat162float(h1));
    __nv_bfloat16 l2 = __float2bfloat16(a.z - __bfloat162float(h2));
    __nv_bfloat16 l3 = __float2bfloat16(a.w - __bfloat162float(h3));
    __nv_bfloat162 hp0(h0, h1), hp1(h2, h3), lp0(l0, l1), lp1(l2, l3);
    hi.x = *(uint32_t*)&hp0; hi.y = *(uint32_t*)&hp1;
    lo.x = *(uint32_t*)&lp0; lo.y = *(uint32_t*)&lp1;
}
__device__ __forceinline__ void pack_hl(float a, float b, uint32_t& hi, uint32_t& lo){
    __nv_bfloat16 ha = __float2bfloat16(a), hb = __float2bfloat16(b);
    __nv_bfloat162 hp(ha, hb);
    hi = *(uint32_t*)&hp;
    __nv_bfloat162 lp(__float2bfloat16(a - __bfloat162float(ha)),
                      __float2bfloat16(b - __bfloat162float(hb)));
    lo = *(uint32_t*)&lp;
}

#define BK  32
#define SK  40   // padded k-stride (80B) for gemm tiles

// ---------------------------------------------------------------------------
// GEMM core: 128x128 CTA tile, BK=32, 8 warps (2m x 4n), bf16 3-pass split.
// ---------------------------------------------------------------------------
struct GemmSmem {
    __nv_bfloat16 Ah[128*SK];
    __nv_bfloat16 Al[128*SK];
    __nv_bfloat16 Bh[128*SK];
    __nv_bfloat16 Bl[128*SK];
};

__device__ __forceinline__ void gemm_mma_chunk(
    uint32_t sAh, uint32_t sAl, uint32_t sBh, uint32_t sBl,
    uint32_t aoff, uint32_t boff, float acc[4][4][4])
{
    #pragma unroll
    for (int pass = 0; pass < 3; pass++) {
        uint32_t sA = (pass == 2) ? sAl : sAh;
        uint32_t sB = (pass == 1) ? sBl : sBh;
        #pragma unroll
        for (int ks = 0; ks < 2; ks++) {
            uint32_t af[4][4], bf[4][2];
            #pragma unroll
            for (int mt = 0; mt < 4; mt++)
                ldsm_x4(af[mt], sA + aoff + (mt*16*SK + ks*16)*2);
            #pragma unroll
            for (int nt = 0; nt < 4; nt++)
                ldsm_x2(bf[nt], sB + boff + (nt*8*SK + ks*16)*2);
            #pragma unroll
            for (int mt = 0; mt < 4; mt++)
                #pragma unroll
                for (int nt = 0; nt < 4; nt++)
                    mma16816(acc[mt][nt], af[mt], bf[nt]);
        }
    }
}

// ---------------------------------------------------------------------------
// Kernel 1: QKV projection, register-prefetch pipelined.
// ---------------------------------------------------------------------------
__global__ __launch_bounds__(256) void qkv_mma(
    const float* __restrict__ x,
    const float* __restrict__ Wq, const float* __restrict__ bq,
    const float* __restrict__ Wk, const float* __restrict__ bk,
    const float* __restrict__ Wv, const float* __restrict__ bv)
{
    __shared__ GemmSmem sm;
    int tid = threadIdx.x, wid = tid >> 5, lane = tid & 31;
    int wm = wid >> 2, wn = wid & 3;
    int mt_ = blockIdx.x, nt_ = blockIdx.y;
    int which = nt_ >> 3, hbase = (nt_ & 7) * 2;
    const int m0 = mt_ * 128;

    const float* W; const float* bias; float* out;
    if (which == 0)      { W = Wq; bias = bq; out = g_q; }
    else if (which == 1) { W = Wk; bias = bk; out = g_k; }
    else                 { W = Wv; bias = bv; out = g_v; }

    uint32_t sAh = smem_u32(sm.Ah), sAl = smem_u32(sm.Al);
    uint32_t sBh = smem_u32(sm.Bh), sBl = smem_u32(sm.Bl);
    uint32_t aoff = ((wm*64 + (lane & 15)) * SK + ((lane >> 4) << 3)) * 2;
    uint32_t boff = ((wn*32 + (lane & 7)) * SK + (((lane >> 3) & 1) << 3)) * 2;

    float acc[4][4][4] = {};
    float4 ra[4], rb[4];

    #pragma unroll
    for (int it = 0; it < 4; it++) {
        int g = tid + it*256;
        int r = g >> 3, kb = (g & 7) << 2;
        ra[it] = *(const float4*)(x + (size_t)(m0 + r) * C_ + kb);
        int n = g & 127, k4 = (g >> 7) << 2;
        int h = hbase + (n >> 6), d = n & 63;
        const float* wp = W + (size_t)h * C_ * HD_ + (size_t)k4 * HD_ + d;
        rb[it] = make_float4(wp[0], wp[HD_], wp[2*HD_], wp[3*HD_]);
    }

    for (int kc = 0; kc < 32; kc++) {
        #pragma unroll
        for (int it = 0; it < 4; it++) {
            int g = tid + it*256;
            int r = g >> 3, kb = (g & 7) << 2;
            uint2 hi, lo; split_pack(ra[it], hi, lo);
            *(uint2*)&sm.Ah[r*SK + kb] = hi;
            *(uint2*)&sm.Al[r*SK + kb] = lo;
            int n = g & 127, k4 = (g >> 7) << 2;
            split_pack(rb[it], hi, lo);
            *(uint2*)&sm.Bh[n*SK + k4] = hi;
            *(uint2*)&sm.Bl[n*SK + k4] = lo;
        }
        __syncthreads();
        if (kc + 1 < 32) {
            int k0 = (kc + 1) * BK;
            #pragma unroll
            for (int it = 0; it < 4; it++) {
                int g = tid + it*256;
                int r = g >> 3, kb = (g & 7) << 2;
                ra[it] = *(const float4*)(x + (size_t)(m0 + r) * C_ + k0 + kb);
                int n = g & 127, k4 = (g >> 7) << 2;
                int h = hbase + (n >> 6), d = n & 63;
                const float* wp = W + (size_t)h * C_ * HD_ + (size_t)(k0 + k4) * HD_ + d;
                rb[it] = make_float4(wp[0], wp[HD_], wp[2*HD_], wp[3*HD_]);
            }
        }
        gemm_mma_chunk(sAh, sAl, sBh, sBl, aoff, boff, acc);
        __syncthreads();
    }

    #pragma unroll
    for (int mt = 0; mt < 4; mt++) {
        int mrow = m0 + wm*64 + mt*16 + (lane >> 2);
        #pragma unroll
        for (int half = 0; half < 2; half++) {
            int m = mrow + half*8;
            int b_ = m >> 11, t = m & (T_-1);
            #pragma unroll
            for (int nt = 0; nt < 4; nt++) {
                int n = wn*32 + nt*8 + ((lane & 3) << 1);
                int h = hbase + (n >> 6), d = n & 63;
                float c0 = acc[mt][nt][half*2+0] + bias[h*HD_ + d];
                float c1 = acc[mt][nt][half*2+1] + bias[h*HD_ + d + 1];
                *(float2*)&out[(((size_t)(b_*H_ + h))*T_ + t)*HD_ + d] = make_float2(c0, c1);
            }
        }
    }
}

// ---------------------------------------------------------------------------
// Kernel 2: tensor-core causal flash attention.
//  CTA: 128 q-rows, 8 warps x 16 rows; K/V tiles of 64 keys.
//  S = QK^T bf16 3-pass; PV bf16 3-pass (P hi/lo x V hi/lo, drop lo*lo).
// ---------------------------------------------------------------------------
#define SKA 72

__global__ __launch_bounds__(256) void attn_mma()
{
    __shared__ __nv_bfloat16 Kh[64*SKA];
    __shared__ __nv_bfloat16 Kl[64*SKA];
    __shared__ __nv_bfloat16 Vh[64*SKA];
    __shared__ __nv_bfloat16 Vl[64*SKA];

    int tid = threadIdx.x, wid = tid >> 5, lane = tid & 31;
    int qt = 15 - blockIdx.x;             // big tiles first
    int bh = blockIdx.y;
    const float* Qg = g_q + (size_t)bh * T_ * HD_;
    const float* Kg = g_k + (size_t)bh * T_ * HD_;
    const float* Vg = g_v + (size_t)bh * T_ * HD_;

    uint32_t sKh = smem_u32(Kh), sKl = smem_u32(Kl);
    uint32_t sVh = smem_u32(Vh), sVl = smem_u32(Vl);

    int r0 = lane >> 2, c0 = (lane & 3) << 1;
    int wrow = qt*128 + wid*16;
    int row0 = wrow + r0;

    // Q a-frags (hi/lo), loaded once
    uint32_t qh[4][4], ql[4][4];
    #pragma unroll
    for (int ks = 0; ks < 4; ks++) {
        #pragma unroll
        for (int p = 0; p < 4; p++) {
            int rr = row0 + ((p & 1) << 3);
            int cc = ks*16 + c0 + ((p >> 1) << 3);
            float2 v = *(const float2*)(Qg + (size_t)rr * HD_ + cc);
            pack_hl(v.x, v.y, qh[ks][p], ql[ks][p]);
        }
    }

    float o[8][4];
    #pragma unroll
    for (int i = 0; i < 8; i++) { o[i][0]=o[i][1]=o[i][2]=o[i][3]=0.f; }
    float m_i[2] = {-1e30f, -1e30f}, l_i[2] = {0.f, 0.f};

    int sKr = tid >> 2, dB = (tid & 3) << 4;
    int jmax = 2*qt + 1;

    float4 kreg[4], vreg[4];
    #pragma unroll
    for (int u = 0; u < 4; u++) {
        kreg[u] = *(const float4*)(Kg + (size_t)sKr * HD_ + dB + u*4);
        vreg[u] = *(const float4*)(Vg + (size_t)sKr * HD_ + dB + u*4);
    }

    for (int j = 0; j <= jmax; j++) {
        // fill smem tiles from prefetch regs; V stored transposed [d][s] hi/lo
        #pragma unroll
        for (int u = 0; u < 4; u++) {
            uint2 hi, lo; split_pack(kreg[u], hi, lo);
            *(uint2*)&Kh[sKr*SKA + dB + u*4] = hi;
            *(uint2*)&Kl[sKr*SKA + dB + u*4] = lo;
            float vv[4] = {vreg[u].x, vreg[u].y, vreg[u].z, vreg[u].w};
            #pragma unroll
            for (int e = 0; e < 4; e++) {
                __nv_bfloat16 vh = __float2bfloat16(vv[e]);
                Vh[(dB + u*4 + e)*SKA + sKr] = vh;
                Vl[(dB + u*4 + e)*SKA + sKr] =
                    __float2bfloat16(vv[e] - __bfloat162float(vh));
            }
        }
        __syncthreads();
        if (j < jmax) {
            const float* Kn = Kg + (size_t)(j+1)*64*HD_;
            const float* Vn = Vg + (size_t)(j+1)*64*HD_;
            #pragma unroll
            for (int u = 0; u < 4; u++) {
                kreg[u] = *(const float4*)(Kn + (size_t)sKr * HD_ + dB + u*4);
                vreg[u] = *(const float4*)(Vn + (size_t)sKr * HD_ + dB + u*4);
            }
        }

        bool dead = (j*64) > (wrow + 15);
        if (!dead) {
            // S = Q K^T, 3-pass
            float c[8][4] = {};
            #pragma unroll
            for (int ks = 0; ks < 4; ks++) {
                uint32_t bfh[8][2], bfl[8][2];
                #pragma unroll
                for (int nt = 0; nt < 8; nt++) {
                    uint32_t off = ((nt*8 + (lane & 7))*SKA + ks*16 + ((lane >> 3) & 1)*8) * 2;
                    ldsm_x2(bfh[nt], sKh + off);
                    ldsm_x2(bfl[nt], sKl + off);
                }
                #pragma unroll
                for (int nt = 0; nt < 8; nt++) {
                    mma16816(c[nt], qh[ks], bfh[nt]);
                    mma16816(c[nt], qh[ks], bfl[nt]);
                    mma16816(c[nt], ql[ks], bfh[nt]);
                }
            }
            // scale + causal mask
            bool dflag = (j >= 2*qt);
            #pragma unroll
            for (int nt = 0; nt < 8; nt++) {
                #pragma unroll
                for (int e = 0; e < 4; e++) {
                    float s = c[nt][e] * 0.03125f;
                    if (dflag) {
                        int col = j*64 + nt*8 + c0 + (e & 1);
                        int row = row0 + ((e >> 1) << 3);
                        if (col > row) s = -1e30f;
                    }
                    c[nt][e] = s;
                }
            }
            // online softmax (rows r0, r0+8)
            #pragma unroll
            for (int r = 0; r < 2; r++) {
                float mx = -1e30f;
                #pragma unroll
                for (int nt = 0; nt < 8; nt++)
                    mx = fmaxf(mx, fmaxf(c[nt][2*r], c[nt][2*r+1]));
                mx = fmaxf(mx, __shfl_xor_sync(0xffffffffu, mx, 1));
                mx = fmaxf(mx, __shfl_xor_sync(0xffffffffu, mx, 2));
                float mnew = fmaxf(m_i[r], mx);
                float alpha = __expf(m_i[r] - mnew);
                m_i[r] = mnew;
                float rs = 0.f;
                #pragma unroll
                for (int nt = 0; nt < 8; nt++) {
                    float p0 = __expf(c[nt][2*r]   - mnew);
                    float p1 = __expf(c[nt][2*r+1] - mnew);
                    c[nt][2*r] = p0; c[nt][2*r+1] = p1;
                    rs += p0 + p1;
                }
                rs += __shfl_xor_sync(0xffffffffu, rs, 1);
                rs += __shfl_xor_sync(0xffffffffu, rs, 2);
                l_i[r] = l_i[r]*alpha + rs;
                #pragma unroll
                for (int nt = 0; nt < 8; nt++) {
                    o[nt][2*r]   *= alpha;
                    o[nt][2*r+1] *= alpha;
                }
            }
            // O += P V  (3-pass: Ph*Vh + Ph*Vl + Pl*Vh)
            #pragma unroll
            for (int ks = 0; ks < 4; ks++) {
                uint32_t ph[4], pl[4];
                pack_hl(c[2*ks][0],   c[2*ks][1],   ph[0], pl[0]);
                pack_hl(c[2*ks][2],   c[2*ks][3],   ph[1], pl[1]);
                pack_hl(c[2*ks+1][0], c[2*ks+1][1], ph[2], pl[2]);
                pack_hl(c[2*ks+1][2], c[2*ks+1][3], ph[3], pl[3]);
                uint32_t bvh[8][2], bvl[8][2];
                #pragma unroll
                for (int nt = 0; nt < 8; nt++) {
                    uint32_t off = ((nt*8 + (lane & 7))*SKA + ks*16 + ((lane >> 3) & 1)*8) * 2;
                    ldsm_x2(bvh[nt], sVh + off);
                    ldsm_x2(bvl[nt], sVl + off);
                }
                #pragma unroll
                for (int nt = 0; nt < 8; nt++) {
                    mma16816(o[nt], ph, bvh[nt]);
                    mma16816(o[nt], ph, bvl[nt]);
                    mma16816(o[nt], pl, bvh[nt]);
                }
            }
        }
        __syncthreads();
    }

    float inv0 = 1.0f / l_i[0], inv1 = 1.0f / l_i[1];
    float* Og = g_att + (size_t)bh * T_ * HD_;
    #pragma unroll
    for (int nt = 0; nt < 8; nt++) {
        int d = nt*8 + c0;
        *(float2*)&Og[(size_t)row0*HD_ + d] =
            make_float2(o[nt][0]*inv0, o[nt][1]*inv0);
        *(float2*)&Og[(size_t)(row0+8)*HD_ + d] =
            make_float2(o[nt][2]*inv1, o[nt][3]*inv1);
    }
}

// ---------------------------------------------------------------------------
// Kernel 3: output projection, register-prefetch pipelined.
// ---------------------------------------------------------------------------
__global__ __launch_bounds__(256) void proj_mma(
    const float* __restrict__ Wp, const float* __restrict__ bp,
    float* __restrict__ outp)
{
    __shared__ GemmSmem sm;
    int tid = threadIdx.x, wid = tid >> 5, lane = tid & 31;
    int wm = wid >> 2, wn = wid & 3;
    const int m0 = blockIdx.x * 128, n0 = blockIdx.y * 128;

    uint32_t sAh = smem_u32(sm.Ah), sAl = smem_u32(sm.Al);
    uint32_t sBh = smem_u32(sm.Bh), sBl = smem_u32(sm.Bl);
    uint32_t aoff = ((wm*64 + (lane & 15)) * SK + ((lane >> 4) << 3)) * 2;
    uint32_t boff = ((wn*32 + (lane & 7)) * SK + (((lane >> 3) & 1) << 3)) * 2;

    float acc[4][4][4] = {};
    float4 ra[4], rb[4];

    #pragma unroll
    for (int it = 0; it < 4; it++) {
        int g = tid + it*256;
        int r = g >> 3, kb = (g & 7) << 2;
        int m = m0 + r, b_ = m >> 11, t = m & (T_-1);
        int h = kb >> 6, dl = kb & 63;
        ra[it] = *(const float4*)(g_att + (((size_t)(b_*H_ + h))*T_ + t)*HD_ + dl);
        int n = g & 127, k4 = (g >> 7) << 2;
        const float* wp = Wp + (size_t)k4 * C_ + n0 + n;
        rb[it] = make_float4(wp[0], wp[C_], wp[2*C_], wp[3*C_]);
    }

    for (int kc = 0; kc < 32; kc++) {
        #pragma unroll
        for (int it = 0; it < 4; it++) {
            int g = tid + it*256;
            int r = g >> 3, kb = (g & 7) << 2;
            uint2 hi, lo; split_pack(ra[it], hi, lo);
            *(uint2*)&sm.Ah[r*SK + kb] = hi;
            *(uint2*)&sm.Al[r*SK + kb] = lo;
            int n = g & 127, k4 = (g >> 7) << 2;
            split_pack(rb[it], hi, lo);
            *(uint2*)&sm.Bh[n*SK + k4] = hi;
            *(uint2*)&sm.Bl[n*SK + k4] = lo;
        }
        __syncthreads();
        if (kc + 1 < 32) {
            int k0 = (kc + 1) * BK;
            #pragma unroll
            for (int it = 0; it < 4; it++) {
                int g = tid + it*256;
                int r = g >> 3, kb = (g & 7) << 2;
                int m = m0 + r, b_ = m >> 11, t = m & (T_-1);
                int k = k0 + kb, h = k >> 6, dl = k & 63;
                ra[it] = *(const float4*)(g_att + (((size_t)(b_*H_ + h))*T_ + t)*HD_ + dl);
                int n = g & 127, k4 = (g >> 7) << 2;
                const float* wp = Wp + (size_t)(k0 + k4) * C_ + n0 + n;
                rb[it] = make_float4(wp[0], wp[C_], wp[2*C_], wp[3*C_]);
            }
        }
        gemm_mma_chunk(sAh, sAl, sBh, sBl, aoff, boff, acc);
        __syncthreads();
    }

    #pragma unroll
    for (int mt = 0; mt < 4; mt++) {
        int mrow = m0 + wm*64 + mt*16 + (lane >> 2);
        #pragma unroll
        for (int half = 0; half < 2; half++) {
            int m = mrow + half*8;
            #pragma unroll
            for (int nt = 0; nt < 4; nt++) {
                int n = wn*32 + nt*8 + ((lane & 3) << 1);
                float c0 = acc[mt][nt][half*2+0] + bp[n0 + n];
                float c1 = acc[mt][nt][half*2+1] + bp[n0 + n + 1];
                *(float2*)&outp[(size_t)m*C_ + n0 + n] = make_float2(c0, c1);
            }
        }
    }
}

// ---------------------------------------------------------------------------
extern "C" void kernel_launch(void* const* d_in, const int* in_sizes, int n_in,
                              void* d_out, int out_size)
{
    const float* x  = (const float*)d_in[0];
    const float* Wq = (const float*)d_in[1];
    const float* bq = (const float*)d_in[2];
    const float* Wk = (const float*)d_in[3];
    const float* bk = (const float*)d_in[4];
    const float* Wv = (const float*)d_in[5];
    const float* bv = (const float*)d_in[6];
    const float* Wp = (const float*)d_in[7];
    const float* bp = (const float*)d_in[8];
    float* out = (float*)d_out;

    qkv_mma<<<dim3(64, 24), 256>>>(x, Wq, bq, Wk, bk, Wv, bv);
    attn_mma<<<dim3(16, 64), 256>>>();
    proj_mma<<<dim3(64, 8), 256>>>(Wp, bp, out);
}

// round 6
// speedup vs baseline: 3.5797x; 1.4163x over previous
#include <cuda_runtime.h>
#include <cuda_fp16.h>
#include <math.h>
#include <stdint.h>

#define B_  4
#define T_  2048
#define C_  1024
#define H_  16
#define HD_ 64
#define M_  (B_*T_)   // 8192

// Scratch (allocation-free: __device__ globals)
__device__ float g_q[B_*H_*T_*HD_];
__device__ float g_k[B_*H_*T_*HD_];
__device__ float g_v[B_*H_*T_*HD_];
__device__ float g_att[B_*T_*C_];

// ---------------------------------------------------------------------------
// mma.sync helpers (fp16 HMMA path)
// ---------------------------------------------------------------------------
__device__ __forceinline__ uint32_t smem_u32(const void* p){
    uint32_t a;
    asm("{ .reg .u64 t; cvta.to.shared.u64 t, %1; cvt.u32.u64 %0, t; }"
        : "=r"(a) : "l"(p));
    return a;
}
__device__ __forceinline__ void ldsm_x4(uint32_t* r, uint32_t addr){
    asm volatile("ldmatrix.sync.aligned.m8n8.x4.shared.b16 {%0,%1,%2,%3}, [%4];"
        : "=r"(r[0]), "=r"(r[1]), "=r"(r[2]), "=r"(r[3]) : "r"(addr));
}
__device__ __forceinline__ void ldsm_x2(uint32_t* r, uint32_t addr){
    asm volatile("ldmatrix.sync.aligned.m8n8.x2.shared.b16 {%0,%1}, [%2];"
        : "=r"(r[0]), "=r"(r[1]) : "r"(addr));
}
__device__ __forceinline__ void mma16816(float* c, const uint32_t* a, const uint32_t* b){
    asm volatile(
        "mma.sync.aligned.m16n8k16.row.col.f32.f16.f16.f32 "
        "{%0,%1,%2,%3}, {%4,%5,%6,%7}, {%8,%9}, {%0,%1,%2,%3};"
        : "+f"(c[0]), "+f"(c[1]), "+f"(c[2]), "+f"(c[3])
        : "r"(a[0]), "r"(a[1]), "r"(a[2]), "r"(a[3]), "r"(b[0]), "r"(b[1]));
}

// split fp32x4 -> fp16 hi + fp16 residual
__device__ __forceinline__ void split_pack_h(float4 a, uint2& hi, uint2& lo){
    __half2 h0 = __floats2half2_rn(a.x, a.y);
    __half2 h1 = __floats2half2_rn(a.z, a.w);
    __half2 l0 = __floats2half2_rn(a.x - __low2float(h0), a.y - __high2float(h0));
    __half2 l1 = __floats2half2_rn(a.z - __low2float(h1), a.w - __high2float(h1));
    hi.x = *(uint32_t*)&h0; hi.y = *(uint32_t*)&h1;
    lo.x = *(uint32_t*)&l0; lo.y = *(uint32_t*)&l1;
}
__device__ __forceinline__ uint2 pack4h(float4 a){
    __half2 h0 = __floats2half2_rn(a.x, a.y);
    __half2 h1 = __floats2half2_rn(a.z, a.w);
    uint2 r; r.x = *(uint32_t*)&h0; r.y = *(uint32_t*)&h1;
    return r;
}
__device__ __forceinline__ void pack_hl_h(float a, float b, uint32_t& hi, uint32_t& lo){
    __half2 hp = __floats2half2_rn(a, b);
    hi = *(uint32_t*)&hp;
    __half2 lp = __floats2half2_rn(a - __low2float(hp), b - __high2float(hp));
    lo = *(uint32_t*)&lp;
}

#define BK  32
#define SK  40   // padded k-stride (80B) for gemm tiles

// ---------------------------------------------------------------------------
// GEMM core: 128x128 CTA tile, BK=32, 8 warps (2m x 4n).
// A split hi/lo (2-pass), B single fp16.
// ---------------------------------------------------------------------------
struct GemmSmem {
    __half Ah[128*SK];
    __half Al[128*SK];
    __half Bs[128*SK];
};

__device__ __forceinline__ void gemm_mma_chunk(
    uint32_t sAh, uint32_t sAl, uint32_t sB,
    uint32_t aoff, uint32_t boff, float acc[4][4][4])
{
    uint32_t bf[2][4][2];
    #pragma unroll
    for (int ks = 0; ks < 2; ks++)
        #pragma unroll
        for (int nt = 0; nt < 4; nt++)
            ldsm_x2(bf[ks][nt], sB + boff + (nt*8*SK + ks*16)*2);

    #pragma unroll
    for (int pass = 0; pass < 2; pass++) {
        uint32_t sA = pass ? sAl : sAh;
        #pragma unroll
        for (int ks = 0; ks < 2; ks++) {
            uint32_t af[4][4];
            #pragma unroll
            for (int mt = 0; mt < 4; mt++)
                ldsm_x4(af[mt], sA + aoff + (mt*16*SK + ks*16)*2);
            #pragma unroll
            for (int mt = 0; mt < 4; mt++)
                #pragma unroll
                for (int nt = 0; nt < 4; nt++)
                    mma16816(acc[mt][nt], af[mt], bf[ks][nt]);
        }
    }
}

// ---------------------------------------------------------------------------
// Kernel 1: QKV projection, register-prefetch pipelined.
// ---------------------------------------------------------------------------
__global__ __launch_bounds__(256) void qkv_mma(
    const float* __restrict__ x,
    const float* __restrict__ Wq, const float* __restrict__ bq,
    const float* __restrict__ Wk, const float* __restrict__ bk,
    const float* __restrict__ Wv, const float* __restrict__ bv)
{
    __shared__ GemmSmem sm;
    int tid = threadIdx.x, wid = tid >> 5, lane = tid & 31;
    int wm = wid >> 2, wn = wid & 3;
    int mt_ = blockIdx.x, nt_ = blockIdx.y;
    int which = nt_ >> 3, hbase = (nt_ & 7) * 2;
    const int m0 = mt_ * 128;

    const float* W; const float* bias; float* out;
    if (which == 0)      { W = Wq; bias = bq; out = g_q; }
    else if (which == 1) { W = Wk; bias = bk; out = g_k; }
    else                 { W = Wv; bias = bv; out = g_v; }

    uint32_t sAh = smem_u32(sm.Ah), sAl = smem_u32(sm.Al);
    uint32_t sB  = smem_u32(sm.Bs);
    uint32_t aoff = ((wm*64 + (lane & 15)) * SK + ((lane >> 4) << 3)) * 2;
    uint32_t boff = ((wn*32 + (lane & 7)) * SK + (((lane >> 3) & 1) << 3)) * 2;

    float acc[4][4][4] = {};
    float4 ra[4], rb[4];

    #pragma unroll
    for (int it = 0; it < 4; it++) {
        int g = tid + it*256;
        int r = g >> 3, kb = (g & 7) << 2;
        ra[it] = *(const float4*)(x + (size_t)(m0 + r) * C_ + kb);
        int n = g & 127, k4 = (g >> 7) << 2;
        int h = hbase + (n >> 6), d = n & 63;
        const float* wp = W + (size_t)h * C_ * HD_ + (size_t)k4 * HD_ + d;
        rb[it] = make_float4(wp[0], wp[HD_], wp[2*HD_], wp[3*HD_]);
    }

    for (int kc = 0; kc < 32; kc++) {
        #pragma unroll
        for (int it = 0; it < 4; it++) {
            int g = tid + it*256;
            int r = g >> 3, kb = (g & 7) << 2;
            uint2 hi, lo; split_pack_h(ra[it], hi, lo);
            *(uint2*)&sm.Ah[r*SK + kb] = hi;
            *(uint2*)&sm.Al[r*SK + kb] = lo;
            int n = g & 127, k4 = (g >> 7) << 2;
            *(uint2*)&sm.Bs[n*SK + k4] = pack4h(rb[it]);
        }
        __syncthreads();
        if (kc + 1 < 32) {
            int k0 = (kc + 1) * BK;
            #pragma unroll
            for (int it = 0; it < 4; it++) {
                int g = tid + it*256;
                int r = g >> 3, kb = (g & 7) << 2;
                ra[it] = *(const float4*)(x + (size_t)(m0 + r) * C_ + k0 + kb);
                int n = g & 127, k4 = (g >> 7) << 2;
                int h = hbase + (n >> 6), d = n & 63;
                const float* wp = W + (size_t)h * C_ * HD_ + (size_t)(k0 + k4) * HD_ + d;
                rb[it] = make_float4(wp[0], wp[HD_], wp[2*HD_], wp[3*HD_]);
            }
        }
        gemm_mma_chunk(sAh, sAl, sB, aoff, boff, acc);
        __syncthreads();
    }

    #pragma unroll
    for (int mt = 0; mt < 4; mt++) {
        int mrow = m0 + wm*64 + mt*16 + (lane >> 2);
        #pragma unroll
        for (int half = 0; half < 2; half++) {
            int m = mrow + half*8;
            int b_ = m >> 11, t = m & (T_-1);
            #pragma unroll
            for (int nt = 0; nt < 4; nt++) {
                int n = wn*32 + nt*8 + ((lane & 3) << 1);
                int h = hbase + (n >> 6), d = n & 63;
                float c0 = acc[mt][nt][half*2+0] + bias[h*HD_ + d];
                float c1 = acc[mt][nt][half*2+1] + bias[h*HD_ + d + 1];
                *(float2*)&out[(((size_t)(b_*H_ + h))*T_ + t)*HD_ + d] = make_float2(c0, c1);
            }
        }
    }
}

// ---------------------------------------------------------------------------
// Kernel 2: tensor-core causal flash attention.
//  CTA: 128 q-rows, 8 warps x 16 rows; K/V tiles of 64 keys.
//  S = (Qh+Ql) K  (Q split, K single fp16); PV = (Ph+Pl) V  (V single fp16).
// ---------------------------------------------------------------------------
#define SKA 72

__global__ __launch_bounds__(256) void attn_mma()
{
    __shared__ __half Ks[64*SKA];
    __shared__ __half Vt[64*SKA];

    int tid = threadIdx.x, wid = tid >> 5, lane = tid & 31;
    int qt = 15 - blockIdx.x;             // big tiles first
    int bh = blockIdx.y;
    const float* Qg = g_q + (size_t)bh * T_ * HD_;
    const float* Kg = g_k + (size_t)bh * T_ * HD_;
    const float* Vg = g_v + (size_t)bh * T_ * HD_;

    uint32_t sK = smem_u32(Ks), sV = smem_u32(Vt);

    int r0 = lane >> 2, c0 = (lane & 3) << 1;
    int wrow = qt*128 + wid*16;
    int row0 = wrow + r0;

    // Q a-frags (hi/lo), loaded once
    uint32_t qh[4][4], ql[4][4];
    #pragma unroll
    for (int ks = 0; ks < 4; ks++) {
        #pragma unroll
        for (int p = 0; p < 4; p++) {
            int rr = row0 + ((p & 1) << 3);
            int cc = ks*16 + c0 + ((p >> 1) << 3);
            float2 v = *(const float2*)(Qg + (size_t)rr * HD_ + cc);
            pack_hl_h(v.x, v.y, qh[ks][p], ql[ks][p]);
        }
    }

    float o[8][4];
    #pragma unroll
    for (int i = 0; i < 8; i++) { o[i][0]=o[i][1]=o[i][2]=o[i][3]=0.f; }
    float m_i[2] = {-1e30f, -1e30f}, l_i[2] = {0.f, 0.f};

    int sKr = tid >> 2, dB = (tid & 3) << 4;
    int jmax = 2*qt + 1;

    float4 kreg[4], vreg[4];
    #pragma unroll
    for (int u = 0; u < 4; u++) {
        kreg[u] = *(const float4*)(Kg + (size_t)sKr * HD_ + dB + u*4);
        vreg[u] = *(const float4*)(Vg + (size_t)sKr * HD_ + dB + u*4);
    }

    for (int j = 0; j <= jmax; j++) {
        #pragma unroll
        for (int u = 0; u < 4; u++) {
            *(uint2*)&Ks[sKr*SKA + dB + u*4] = pack4h(kreg[u]);
            Vt[(dB + u*4 + 0)*SKA + sKr] = __float2half(vreg[u].x);
            Vt[(dB + u*4 + 1)*SKA + sKr] = __float2half(vreg[u].y);
            Vt[(dB + u*4 + 2)*SKA + sKr] = __float2half(vreg[u].z);
            Vt[(dB + u*4 + 3)*SKA + sKr] = __float2half(vreg[u].w);
        }
        __syncthreads();
        if (j < jmax) {
            const float* Kn = Kg + (size_t)(j+1)*64*HD_;
            const float* Vn = Vg + (size_t)(j+1)*64*HD_;
            #pragma unroll
            for (int u = 0; u < 4; u++) {
                kreg[u] = *(const float4*)(Kn + (size_t)sKr * HD_ + dB + u*4);
                vreg[u] = *(const float4*)(Vn + (size_t)sKr * HD_ + dB + u*4);
            }
        }

        bool dead = (j*64) > (wrow + 15);
        if (!dead) {
            // S = Q K^T, 2-pass (Q split)
            float c[8][4] = {};
            #pragma unroll
            for (int ks = 0; ks < 4; ks++) {
                uint32_t bf[8][2];
                #pragma unroll
                for (int nt = 0; nt < 8; nt++) {
                    uint32_t off = ((nt*8 + (lane & 7))*SKA + ks*16 + ((lane >> 3) & 1)*8) * 2;
                    ldsm_x2(bf[nt], sK + off);
                }
                #pragma unroll
                for (int nt = 0; nt < 8; nt++) {
                    mma16816(c[nt], qh[ks], bf[nt]);
                    mma16816(c[nt], ql[ks], bf[nt]);
                }
            }
            // scale + causal mask
            bool dflag = (j >= 2*qt);
            #pragma unroll
            for (int nt = 0; nt < 8; nt++) {
                #pragma unroll
                for (int e = 0; e < 4; e++) {
                    float s = c[nt][e] * 0.03125f;
                    if (dflag) {
                        int col = j*64 + nt*8 + c0 + (e & 1);
                        int row = row0 + ((e >> 1) << 3);
                        if (col > row) s = -1e30f;
                    }
                    c[nt][e] = s;
                }
            }
            // online softmax (rows r0, r0+8)
            #pragma unroll
            for (int r = 0; r < 2; r++) {
                float mx = -1e30f;
                #pragma unroll
                for (int nt = 0; nt < 8; nt++)
                    mx = fmaxf(mx, fmaxf(c[nt][2*r], c[nt][2*r+1]));
                mx = fmaxf(mx, __shfl_xor_sync(0xffffffffu, mx, 1));
                mx = fmaxf(mx, __shfl_xor_sync(0xffffffffu, mx, 2));
                float mnew = fmaxf(m_i[r], mx);
                float alpha = __expf(m_i[r] - mnew);
                m_i[r] = mnew;
                float rs = 0.f;
                #pragma unroll
                for (int nt = 0; nt < 8; nt++) {
                    float p0 = __expf(c[nt][2*r]   - mnew);
                    float p1 = __expf(c[nt][2*r+1] - mnew);
                    c[nt][2*r] = p0; c[nt][2*r+1] = p1;
                    rs += p0 + p1;
                }
                rs += __shfl_xor_sync(0xffffffffu, rs, 1);
                rs += __shfl_xor_sync(0xffffffffu, rs, 2);
                l_i[r] = l_i[r]*alpha + rs;
                #pragma unroll
                for (int nt = 0; nt < 8; nt++) {
                    o[nt][2*r]   *= alpha;
                    o[nt][2*r+1] *= alpha;
                }
            }
            // O += P V  (2-pass: P split, V single)
            #pragma unroll
            for (int ks = 0; ks < 4; ks++) {
                uint32_t ph[4], pl[4];
                pack_hl_h(c[2*ks][0],   c[2*ks][1],   ph[0], pl[0]);
                pack_hl_h(c[2*ks][2],   c[2*ks][3],   ph[1], pl[1]);
                pack_hl_h(c[2*ks+1][0], c[2*ks+1][1], ph[2], pl[2]);
                pack_hl_h(c[2*ks+1][2], c[2*ks+1][3], ph[3], pl[3]);
                uint32_t bv[8][2];
                #pragma unroll
                for (int nt = 0; nt < 8; nt++) {
                    uint32_t off = ((nt*8 + (lane & 7))*SKA + ks*16 + ((lane >> 3) & 1)*8) * 2;
                    ldsm_x2(bv[nt], sV + off);
                }
                #pragma unroll
                for (int nt = 0; nt < 8; nt++) {
                    mma16816(o[nt], ph, bv[nt]);
                    mma16816(o[nt], pl, bv[nt]);
                }
            }
        }
        __syncthreads();
    }

    float inv0 = 1.0f / l_i[0], inv1 = 1.0f / l_i[1];
    float* Og = g_att + (size_t)bh * T_ * HD_;
    #pragma unroll
    for (int nt = 0; nt < 8; nt++) {
        int d = nt*8 + c0;
        *(float2*)&Og[(size_t)row0*HD_ + d] =
            make_float2(o[nt][0]*inv0, o[nt][1]*inv0);
        *(float2*)&Og[(size_t)(row0+8)*HD_ + d] =
            make_float2(o[nt][2]*inv1, o[nt][3]*inv1);
    }
}

// ---------------------------------------------------------------------------
// Kernel 3: output projection, register-prefetch pipelined.
// ---------------------------------------------------------------------------
__global__ __launch_bounds__(256) void proj_mma(
    const float* __restrict__ Wp, const float* __restrict__ bp,
    float* __restrict__ outp)
{
    __shared__ GemmSmem sm;
    int tid = threadIdx.x, wid = tid >> 5, lane = tid & 31;
    int wm = wid >> 2, wn = wid & 3;
    const int m0 = blockIdx.x * 128, n0 = blockIdx.y * 128;

    uint32_t sAh = smem_u32(sm.Ah), sAl = smem_u32(sm.Al);
    uint32_t sB  = smem_u32(sm.Bs);
    uint32_t aoff = ((wm*64 + (lane & 15)) * SK + ((lane >> 4) << 3)) * 2;
    uint32_t boff = ((wn*32 + (lane & 7)) * SK + (((lane >> 3) & 1) << 3)) * 2;

    float acc[4][4][4] = {};
    float4 ra[4], rb[4];

    #pragma unroll
    for (int it = 0; it < 4; it++) {
        int g = tid + it*256;
        int r = g >> 3, kb = (g & 7) << 2;
        int m = m0 + r, b_ = m >> 11, t = m & (T_-1);
        int h = kb >> 6, dl = kb & 63;
        ra[it] = *(const float4*)(g_att + (((size_t)(b_*H_ + h))*T_ + t)*HD_ + dl);
        int n = g & 127, k4 = (g >> 7) << 2;
        const float* wp = Wp + (size_t)k4 * C_ + n0 + n;
        rb[it] = make_float4(wp[0], wp[C_], wp[2*C_], wp[3*C_]);
    }

    for (int kc = 0; kc < 32; kc++) {
        #pragma unroll
        for (int it = 0; it < 4; it++) {
            int g = tid + it*256;
            int r = g >> 3, kb = (g & 7) << 2;
            uint2 hi, lo; split_pack_h(ra[it], hi, lo);
            *(uint2*)&sm.Ah[r*SK + kb] = hi;
            *(uint2*)&sm.Al[r*SK + kb] = lo;
            int n = g & 127, k4 = (g >> 7) << 2;
            *(uint2*)&sm.Bs[n*SK + k4] = pack4h(rb[it]);
        }
        __syncthreads();
        if (kc + 1 < 32) {
            int k0 = (kc + 1) * BK;
            #pragma unroll
            for (int it = 0; it < 4; it++) {
                int g = tid + it*256;
                int r = g >> 3, kb = (g & 7) << 2;
                int m = m0 + r, b_ = m >> 11, t = m & (T_-1);
                int k = k0 + kb, h = k >> 6, dl = k & 63;
                ra[it] = *(const float4*)(g_att + (((size_t)(b_*H_ + h))*T_ + t)*HD_ + dl);
                int n = g & 127, k4 = (g >> 7) << 2;
                const float* wp = Wp + (size_t)(k0 + k4) * C_ + n0 + n;
                rb[it] = make_float4(wp[0], wp[C_], wp[2*C_], wp[3*C_]);
            }
        }
        gemm_mma_chunk(sAh, sAl, sB, aoff, boff, acc);
        __syncthreads();
    }

    #pragma unroll
    for (int mt = 0; mt < 4; mt++) {
        int mrow = m0 + wm*64 + mt*16 + (lane >> 2);
        #pragma unroll
        for (int half = 0; half < 2; half++) {
            int m = mrow + half*8;
            #pragma unroll
            for (int nt = 0; nt < 4; nt++) {
                int n = wn*32 + nt*8 + ((lane & 3) << 1);
                float c0 = acc[mt][nt][half*2+0] + bp[n0 + n];
                float c1 = acc[mt][nt][half*2+1] + bp[n0 + n + 1];
                *(float2*)&outp[(size_t)m*C_ + n0 + n] = make_float2(c0, c1);
            }
        }
    }
}

// ---------------------------------------------------------------------------
extern "C" void kernel_launch(void* const* d_in, const int* in_sizes, int n_in,
                              void* d_out, int out_size)
{
    const float* x  = (const float*)d_in[0];
    const float* Wq = (const float*)d_in[1];
    const float* bq = (const float*)d_in[2];
    const float* Wk = (const float*)d_in[3];
    const float* bk = (const float*)d_in[4];
    const float* Wv = (const float*)d_in[5];
    const float* bv = (const float*)d_in[6];
    const float* Wp = (const float*)d_in[7];
    const float* bp = (const float*)d_in[8];
    float* out = (float*)d_out;

    qkv_mma<<<dim3(64, 24), 256>>>(x, Wq, bq, Wk, bk, Wv, bv);
    attn_mma<<<dim3(16, 64), 256>>>();
    proj_mma<<<dim3(64, 8), 256>>>(Wp, bp, out);
}

// round 7
// speedup vs baseline: 3.8878x; 1.0861x over previous
#include <cuda_runtime.h>
#include <cuda_fp16.h>
#include <math.h>
#include <stdint.h>

#define B_  4
#define T_  2048
#define C_  1024
#define H_  16
#define HD_ 64
#define M_  (B_*T_)   // 8192

// Scratch (allocation-free: __device__ globals)
__device__ float g_q[B_*H_*T_*HD_];
__device__ float g_k[B_*H_*T_*HD_];
__device__ float g_v[B_*H_*T_*HD_];
__device__ float g_att[B_*T_*C_];

// ---------------------------------------------------------------------------
// mma.sync helpers (fp16 HMMA path)
// ---------------------------------------------------------------------------
__device__ __forceinline__ uint32_t smem_u32(const void* p){
    uint32_t a;
    asm("{ .reg .u64 t; cvta.to.shared.u64 t, %1; cvt.u32.u64 %0, t; }"
        : "=r"(a) : "l"(p));
    return a;
}
__device__ __forceinline__ void ldsm_x4(uint32_t* r, uint32_t addr){
    asm volatile("ldmatrix.sync.aligned.m8n8.x4.shared.b16 {%0,%1,%2,%3}, [%4];"
        : "=r"(r[0]), "=r"(r[1]), "=r"(r[2]), "=r"(r[3]) : "r"(addr));
}
__device__ __forceinline__ void ldsm_x2(uint32_t* r, uint32_t addr){
    asm volatile("ldmatrix.sync.aligned.m8n8.x2.shared.b16 {%0,%1}, [%2];"
        : "=r"(r[0]), "=r"(r[1]) : "r"(addr));
}
__device__ __forceinline__ void mma16816(float* c, const uint32_t* a, const uint32_t* b){
    asm volatile(
        "mma.sync.aligned.m16n8k16.row.col.f32.f16.f16.f32 "
        "{%0,%1,%2,%3}, {%4,%5,%6,%7}, {%8,%9}, {%0,%1,%2,%3};"
        : "+f"(c[0]), "+f"(c[1]), "+f"(c[2]), "+f"(c[3])
        : "r"(a[0]), "r"(a[1]), "r"(a[2]), "r"(a[3]), "r"(b[0]), "r"(b[1]));
}

// split fp32x4 -> fp16 hi + fp16 residual
__device__ __forceinline__ void split_pack_h(float4 a, uint2& hi, uint2& lo){
    __half2 h0 = __floats2half2_rn(a.x, a.y);
    __half2 h1 = __floats2half2_rn(a.z, a.w);
    __half2 l0 = __floats2half2_rn(a.x - __low2float(h0), a.y - __high2float(h0));
    __half2 l1 = __floats2half2_rn(a.z - __low2float(h1), a.w - __high2float(h1));
    hi.x = *(uint32_t*)&h0; hi.y = *(uint32_t*)&h1;
    lo.x = *(uint32_t*)&l0; lo.y = *(uint32_t*)&l1;
}
__device__ __forceinline__ uint2 pack4h(float4 a){
    __half2 h0 = __floats2half2_rn(a.x, a.y);
    __half2 h1 = __floats2half2_rn(a.z, a.w);
    uint2 r; r.x = *(uint32_t*)&h0; r.y = *(uint32_t*)&h1;
    return r;
}
__device__ __forceinline__ void pack_hl_h(float a, float b, uint32_t& hi, uint32_t& lo){
    __half2 hp = __floats2half2_rn(a, b);
    hi = *(uint32_t*)&hp;
    __half2 lp = __floats2half2_rn(a - __low2float(hp), b - __high2float(hp));
    lo = *(uint32_t*)&lp;
}

#define BK  32
#define SK  40                 // padded k-stride (80B)
#define BUF_H (3*128*SK)       // halves per gemm buffer (Ah|Al|Bs)
#define GEMM_SMEM (2*BUF_H*2)  // bytes, two buffers = 61440

__device__ __forceinline__ void gemm_mma_chunk(
    uint32_t sAh, uint32_t sAl, uint32_t sB,
    uint32_t aoff, uint32_t boff, float acc[4][4][4])
{
    uint32_t bf[2][4][2];
    #pragma unroll
    for (int ks = 0; ks < 2; ks++)
        #pragma unroll
        for (int nt = 0; nt < 4; nt++)
            ldsm_x2(bf[ks][nt], sB + boff + (nt*8*SK + ks*16)*2);

    #pragma unroll
    for (int pass = 0; pass < 2; pass++) {
        uint32_t sA = pass ? sAl : sAh;
        #pragma unroll
        for (int ks = 0; ks < 2; ks++) {
            uint32_t af[4][4];
            #pragma unroll
            for (int mt = 0; mt < 4; mt++)
                ldsm_x4(af[mt], sA + aoff + (mt*16*SK + ks*16)*2);
            #pragma unroll
            for (int mt = 0; mt < 4; mt++)
                #pragma unroll
                for (int nt = 0; nt < 4; nt++)
                    mma16816(acc[mt][nt], af[mt], bf[ks][nt]);
        }
    }
}

// ---------------------------------------------------------------------------
// Kernel 1: QKV projection, double-buffered, one barrier per chunk.
// ---------------------------------------------------------------------------
__global__ __launch_bounds__(256) void qkv_mma(
    const float* __restrict__ x,
    const float* __restrict__ Wq, const float* __restrict__ bq,
    const float* __restrict__ Wk, const float* __restrict__ bk,
    const float* __restrict__ Wv, const float* __restrict__ bv)
{
    extern __shared__ __half dynsm[];
    int tid = threadIdx.x, wid = tid >> 5, lane = tid & 31;
    int wm = wid >> 2, wn = wid & 3;
    int mt_ = blockIdx.x, nt_ = blockIdx.y;
    int which = nt_ >> 3, hbase = (nt_ & 7) * 2;
    const int m0 = mt_ * 128;

    const float* W; const float* bias; float* out;
    if (which == 0)      { W = Wq; bias = bq; out = g_q; }
    else if (which == 1) { W = Wk; bias = bk; out = g_k; }
    else                 { W = Wv; bias = bv; out = g_v; }

    uint32_t sbase = smem_u32(dynsm);
    uint32_t aoff = ((wm*64 + (lane & 15)) * SK + ((lane >> 4) << 3)) * 2;
    uint32_t boff = ((wn*32 + (lane & 7)) * SK + (((lane >> 3) & 1) << 3)) * 2;

    float acc[4][4][4] = {};
    float4 ra[4], rb[4];

    // load chunk 0
    #pragma unroll
    for (int it = 0; it < 4; it++) {
        int g = tid + it*256;
        int r = g >> 3, kb = (g & 7) << 2;
        ra[it] = *(const float4*)(x + (size_t)(m0 + r) * C_ + kb);
        int n = g & 127, k4 = (g >> 7) << 2;
        int h = hbase + (n >> 6), d = n & 63;
        const float* wp = W + (size_t)h * C_ * HD_ + (size_t)k4 * HD_ + d;
        rb[it] = make_float4(wp[0], wp[HD_], wp[2*HD_], wp[3*HD_]);
    }
    // fill buffer 0
    {
        __half* Ah = dynsm;          __half* Al = Ah + 128*SK;
        __half* Bs = Ah + 2*128*SK;
        #pragma unroll
        for (int it = 0; it < 4; it++) {
            int g = tid + it*256;
            int r = g >> 3, kb = (g & 7) << 2;
            uint2 hi, lo; split_pack_h(ra[it], hi, lo);
            *(uint2*)&Ah[r*SK + kb] = hi;
            *(uint2*)&Al[r*SK + kb] = lo;
            int n = g & 127, k4 = (g >> 7) << 2;
            *(uint2*)&Bs[n*SK + k4] = pack4h(rb[it]);
        }
    }
    // load chunk 1
    #pragma unroll
    for (int it = 0; it < 4; it++) {
        int g = tid + it*256;
        int r = g >> 3, kb = (g & 7) << 2;
        ra[it] = *(const float4*)(x + (size_t)(m0 + r) * C_ + BK + kb);
        int n = g & 127, k4 = (g >> 7) << 2;
        int h = hbase + (n >> 6), d = n & 63;
        const float* wp = W + (size_t)h * C_ * HD_ + (size_t)(BK + k4) * HD_ + d;
        rb[it] = make_float4(wp[0], wp[HD_], wp[2*HD_], wp[3*HD_]);
    }
    __syncthreads();

    for (int kc = 0; kc < 32; kc++) {
        int nxt = kc + 1;
        if (nxt < 32) {
            __half* Ah = dynsm + (nxt & 1)*BUF_H;
            __half* Al = Ah + 128*SK;
            __half* Bs = Ah + 2*128*SK;
            #pragma unroll
            for (int it = 0; it < 4; it++) {
                int g = tid + it*256;
                int r = g >> 3, kb = (g & 7) << 2;
                uint2 hi, lo; split_pack_h(ra[it], hi, lo);
                *(uint2*)&Ah[r*SK + kb] = hi;
                *(uint2*)&Al[r*SK + kb] = lo;
                int n = g & 127, k4 = (g >> 7) << 2;
                *(uint2*)&Bs[n*SK + k4] = pack4h(rb[it]);
            }
        }
        if (nxt + 1 < 32) {
            int k0 = (nxt + 1) * BK;
            #pragma unroll
            for (int it = 0; it < 4; it++) {
                int g = tid + it*256;
                int r = g >> 3, kb = (g & 7) << 2;
                ra[it] = *(const float4*)(x + (size_t)(m0 + r) * C_ + k0 + kb);
                int n = g & 127, k4 = (g >> 7) << 2;
                int h = hbase + (n >> 6), d = n & 63;
                const float* wp = W + (size_t)h * C_ * HD_ + (size_t)(k0 + k4) * HD_ + d;
                rb[it] = make_float4(wp[0], wp[HD_], wp[2*HD_], wp[3*HD_]);
            }
        }
        uint32_t sb = sbase + (kc & 1)*BUF_H*2;
        gemm_mma_chunk(sb, sb + 128*SK*2, sb + 2*128*SK*2, aoff, boff, acc);
        __syncthreads();
    }

    #pragma unroll
    for (int mt = 0; mt < 4; mt++) {
        int mrow = m0 + wm*64 + mt*16 + (lane >> 2);
        #pragma unroll
        for (int half = 0; half < 2; half++) {
            int m = mrow + half*8;
            int b_ = m >> 11, t = m & (T_-1);
            #pragma unroll
            for (int nt = 0; nt < 4; nt++) {
                int n = wn*32 + nt*8 + ((lane & 3) << 1);
                int h = hbase + (n >> 6), d = n & 63;
                float c0 = acc[mt][nt][half*2+0] + bias[h*HD_ + d];
                float c1 = acc[mt][nt][half*2+1] + bias[h*HD_ + d + 1];
                *(float2*)&out[(((size_t)(b_*H_ + h))*T_ + t)*HD_ + d] = make_float2(c0, c1);
            }
        }
    }
}

// ---------------------------------------------------------------------------
// Kernel 2: tensor-core causal flash attention, double-buffered K/V.
// ---------------------------------------------------------------------------
#define SKA 72

__global__ __launch_bounds__(256) void attn_mma()
{
    __shared__ __half Ks[2][64*SKA];
    __shared__ __half Vt[2][64*SKA];

    int tid = threadIdx.x, wid = tid >> 5, lane = tid & 31;
    int qt = 15 - blockIdx.x;
    int bh = blockIdx.y;
    const float* Qg = g_q + (size_t)bh * T_ * HD_;
    const float* Kg = g_k + (size_t)bh * T_ * HD_;
    const float* Vg = g_v + (size_t)bh * T_ * HD_;

    uint32_t sK0 = smem_u32(Ks[0]), sK1 = smem_u32(Ks[1]);
    uint32_t sV0 = smem_u32(Vt[0]), sV1 = smem_u32(Vt[1]);

    int r0 = lane >> 2, c0 = (lane & 3) << 1;
    int wrow = qt*128 + wid*16;
    int row0 = wrow + r0;

    // Q a-frags (hi/lo), loaded once
    uint32_t qh[4][4], ql[4][4];
    #pragma unroll
    for (int ks = 0; ks < 4; ks++) {
        #pragma unroll
        for (int p = 0; p < 4; p++) {
            int rr = row0 + ((p & 1) << 3);
            int cc = ks*16 + c0 + ((p >> 1) << 3);
            float2 v = *(const float2*)(Qg + (size_t)rr * HD_ + cc);
            pack_hl_h(v.x, v.y, qh[ks][p], ql[ks][p]);
        }
    }

    float o[8][4];
    #pragma unroll
    for (int i = 0; i < 8; i++) { o[i][0]=o[i][1]=o[i][2]=o[i][3]=0.f; }
    float m_i[2] = {-1e30f, -1e30f}, l_i[2] = {0.f, 0.f};

    int sKr = tid >> 2, dB = (tid & 3) << 4;
    int jmax = 2*qt + 1;

    float4 kreg[4], vreg[4];
    // load tile 0
    #pragma unroll
    for (int u = 0; u < 4; u++) {
        kreg[u] = *(const float4*)(Kg + (size_t)sKr * HD_ + dB + u*4);
        vreg[u] = *(const float4*)(Vg + (size_t)sKr * HD_ + dB + u*4);
    }
    // fill buffer 0
    #pragma unroll
    for (int u = 0; u < 4; u++) {
        *(uint2*)&Ks[0][sKr*SKA + dB + u*4] = pack4h(kreg[u]);
        Vt[0][(dB + u*4 + 0)*SKA + sKr] = __float2half(vreg[u].x);
        Vt[0][(dB + u*4 + 1)*SKA + sKr] = __float2half(vreg[u].y);
        Vt[0][(dB + u*4 + 2)*SKA + sKr] = __float2half(vreg[u].z);
        Vt[0][(dB + u*4 + 3)*SKA + sKr] = __float2half(vreg[u].w);
    }
    // load tile 1
    if (jmax >= 1) {
        #pragma unroll
        for (int u = 0; u < 4; u++) {
            kreg[u] = *(const float4*)(Kg + (size_t)(64 + sKr) * HD_ + dB + u*4);
            vreg[u] = *(const float4*)(Vg + (size_t)(64 + sKr) * HD_ + dB + u*4);
        }
    }
    __syncthreads();

    for (int j = 0; j <= jmax; j++) {
        int nxt = j + 1;
        if (nxt <= jmax) {
            int b = nxt & 1;
            #pragma unroll
            for (int u = 0; u < 4; u++) {
                *(uint2*)&Ks[b][sKr*SKA + dB + u*4] = pack4h(kreg[u]);
                Vt[b][(dB + u*4 + 0)*SKA + sKr] = __float2half(vreg[u].x);
                Vt[b][(dB + u*4 + 1)*SKA + sKr] = __float2half(vreg[u].y);
                Vt[b][(dB + u*4 + 2)*SKA + sKr] = __float2half(vreg[u].z);
                Vt[b][(dB + u*4 + 3)*SKA + sKr] = __float2half(vreg[u].w);
            }
        }
        if (nxt + 1 <= jmax) {
            const float* Kn = Kg + (size_t)(nxt+1)*64*HD_;
            const float* Vn = Vg + (size_t)(nxt+1)*64*HD_;
            #pragma unroll
            for (int u = 0; u < 4; u++) {
                kreg[u] = *(const float4*)(Kn + (size_t)sKr * HD_ + dB + u*4);
                vreg[u] = *(const float4*)(Vn + (size_t)sKr * HD_ + dB + u*4);
            }
        }

        bool dead = (j*64) > (wrow + 15);
        if (!dead) {
            uint32_t sK = (j & 1) ? sK1 : sK0;
            uint32_t sV = (j & 1) ? sV1 : sV0;
            // S = Q K^T, 2-pass (Q split)
            float c[8][4] = {};
            #pragma unroll
            for (int ks = 0; ks < 4; ks++) {
                uint32_t bf[8][2];
                #pragma unroll
                for (int nt = 0; nt < 8; nt++) {
                    uint32_t off = ((nt*8 + (lane & 7))*SKA + ks*16 + ((lane >> 3) & 1)*8) * 2;
                    ldsm_x2(bf[nt], sK + off);
                }
                #pragma unroll
                for (int nt = 0; nt < 8; nt++) {
                    mma16816(c[nt], qh[ks], bf[nt]);
                    mma16816(c[nt], ql[ks], bf[nt]);
                }
            }
            // scale + causal mask
            bool dflag = (j >= 2*qt);
            #pragma unroll
            for (int nt = 0; nt < 8; nt++) {
                #pragma unroll
                for (int e = 0; e < 4; e++) {
                    float s = c[nt][e] * 0.03125f;
                    if (dflag) {
                        int col = j*64 + nt*8 + c0 + (e & 1);
                        int row = row0 + ((e >> 1) << 3);
                        if (col > row) s = -1e30f;
                    }
                    c[nt][e] = s;
                }
            }
            // online softmax (rows r0, r0+8)
            #pragma unroll
            for (int r = 0; r < 2; r++) {
                float mx = -1e30f;
                #pragma unroll
                for (int nt = 0; nt < 8; nt++)
                    mx = fmaxf(mx, fmaxf(c[nt][2*r], c[nt][2*r+1]));
                mx = fmaxf(mx, __shfl_xor_sync(0xffffffffu, mx, 1));
                mx = fmaxf(mx, __shfl_xor_sync(0xffffffffu, mx, 2));
                float mnew = fmaxf(m_i[r], mx);
                float alpha = __expf(m_i[r] - mnew);
                m_i[r] = mnew;
                float rs = 0.f;
                #pragma unroll
                for (int nt = 0; nt < 8; nt++) {
                    float p0 = __expf(c[nt][2*r]   - mnew);
                    float p1 = __expf(c[nt][2*r+1] - mnew);
                    c[nt][2*r] = p0; c[nt][2*r+1] = p1;
                    rs += p0 + p1;
                }
                rs += __shfl_xor_sync(0xffffffffu, rs, 1);
                rs += __shfl_xor_sync(0xffffffffu, rs, 2);
                l_i[r] = l_i[r]*alpha + rs;
                #pragma unroll
                for (int nt = 0; nt < 8; nt++) {
                    o[nt][2*r]   *= alpha;
                    o[nt][2*r+1] *= alpha;
                }
            }
            // O += P V  (2-pass: P split, V single)
            #pragma unroll
            for (int ks = 0; ks < 4; ks++) {
                uint32_t ph[4], pl[4];
                pack_hl_h(c[2*ks][0],   c[2*ks][1],   ph[0], pl[0]);
                pack_hl_h(c[2*ks][2],   c[2*ks][3],   ph[1], pl[1]);
                pack_hl_h(c[2*ks+1][0], c[2*ks+1][1], ph[2], pl[2]);
                pack_hl_h(c[2*ks+1][2], c[2*ks+1][3], ph[3], pl[3]);
                uint32_t bv[8][2];
                #pragma unroll
                for (int nt = 0; nt < 8; nt++) {
                    uint32_t off = ((nt*8 + (lane & 7))*SKA + ks*16 + ((lane >> 3) & 1)*8) * 2;
                    ldsm_x2(bv[nt], sV + off);
                }
                #pragma unroll
                for (int nt = 0; nt < 8; nt++) {
                    mma16816(o[nt], ph, bv[nt]);
                    mma16816(o[nt], pl, bv[nt]);
                }
            }
        }
        __syncthreads();
    }

    float inv0 = 1.0f / l_i[0], inv1 = 1.0f / l_i[1];
    float* Og = g_att + (size_t)bh * T_ * HD_;
    #pragma unroll
    for (int nt = 0; nt < 8; nt++) {
        int d = nt*8 + c0;
        *(float2*)&Og[(size_t)row0*HD_ + d] =
            make_float2(o[nt][0]*inv0, o[nt][1]*inv0);
        *(float2*)&Og[(size_t)(row0+8)*HD_ + d] =
            make_float2(o[nt][2]*inv1, o[nt][3]*inv1);
    }
}

// ---------------------------------------------------------------------------
// Kernel 3: output projection, double-buffered, one barrier per chunk.
// ---------------------------------------------------------------------------
__global__ __launch_bounds__(256) void proj_mma(
    const float* __restrict__ Wp, const float* __restrict__ bp,
    float* __restrict__ outp)
{
    extern __shared__ __half dynsm[];
    int tid = threadIdx.x, wid = tid >> 5, lane = tid & 31;
    int wm = wid >> 2, wn = wid & 3;
    const int m0 = blockIdx.x * 128, n0 = blockIdx.y * 128;

    uint32_t sbase = smem_u32(dynsm);
    uint32_t aoff = ((wm*64 + (lane & 15)) * SK + ((lane >> 4) << 3)) * 2;
    uint32_t boff = ((wn*32 + (lane & 7)) * SK + (((lane >> 3) & 1) << 3)) * 2;

    float acc[4][4][4] = {};
    float4 ra[4], rb[4];

    #pragma unroll
    for (int it = 0; it < 4; it++) {
        int g = tid + it*256;
        int r = g >> 3, kb = (g & 7) << 2;
        int m = m0 + r, b_ = m >> 11, t = m & (T_-1);
        int h = kb >> 6, dl = kb & 63;
        ra[it] = *(const float4*)(g_att + (((size_t)(b_*H_ + h))*T_ + t)*HD_ + dl);
        int n = g & 127, k4 = (g >> 7) << 2;
        const float* wp = Wp + (size_t)k4 * C_ + n0 + n;
        rb[it] = make_float4(wp[0], wp[C_], wp[2*C_], wp[3*C_]);
    }
    {
        __half* Ah = dynsm;          __half* Al = Ah + 128*SK;
        __half* Bs = Ah + 2*128*SK;
        #pragma unroll
        for (int it = 0; it < 4; it++) {
            int g = tid + it*256;
            int r = g >> 3, kb = (g & 7) << 2;
            uint2 hi, lo; split_pack_h(ra[it], hi, lo);
            *(uint2*)&Ah[r*SK + kb] = hi;
            *(uint2*)&Al[r*SK + kb] = lo;
            int n = g & 127, k4 = (g >> 7) << 2;
            *(uint2*)&Bs[n*SK + k4] = pack4h(rb[it]);
        }
    }
    #pragma unroll
    for (int it = 0; it < 4; it++) {
        int g = tid + it*256;
        int r = g >> 3, kb = (g & 7) << 2;
        int m = m0 + r, b_ = m >> 11, t = m & (T_-1);
        int k = BK + kb, h = k >> 6, dl = k & 63;
        ra[it] = *(const float4*)(g_att + (((size_t)(b_*H_ + h))*T_ + t)*HD_ + dl);
        int n = g & 127, k4 = (g >> 7) << 2;
        const float* wp = Wp + (size_t)(BK + k4) * C_ + n0 + n;
        rb[it] = make_float4(wp[0], wp[C_], wp[2*C_], wp[3*C_]);
    }
    __syncthreads();

    for (int kc = 0; kc < 32; kc++) {
        int nxt = kc + 1;
        if (nxt < 32) {
            __half* Ah = dynsm + (nxt & 1)*BUF_H;
            __half* Al = Ah + 128*SK;
            __half* Bs = Ah + 2*128*SK;
            #pragma unroll
            for (int it = 0; it < 4; it++) {
                int g = tid + it*256;
                int r = g >> 3, kb = (g & 7) << 2;
                uint2 hi, lo; split_pack_h(ra[it], hi, lo);
                *(uint2*)&Ah[r*SK + kb] = hi;
                *(uint2*)&Al[r*SK + kb] = lo;
                int n = g & 127, k4 = (g >> 7) << 2;
                *(uint2*)&Bs[n*SK + k4] = pack4h(rb[it]);
            }
        }
        if (nxt + 1 < 32) {
            int k0 = (nxt + 1) * BK;
            #pragma unroll
            for (int it = 0; it < 4; it++) {
                int g = tid + it*256;
                int r = g >> 3, kb = (g & 7) << 2;
                int m = m0 + r, b_ = m >> 11, t = m & (T_-1);
                int k = k0 + kb, h = k >> 6, dl = k & 63;
                ra[it] = *(const float4*)(g_att + (((size_t)(b_*H_ + h))*T_ + t)*HD_ + dl);
                int n = g & 127, k4 = (g >> 7) << 2;
                const float* wp = Wp + (size_t)(k0 + k4) * C_ + n0 + n;
                rb[it] = make_float4(wp[0], wp[C_], wp[2*C_], wp[3*C_]);
            }
        }
        uint32_t sb = sbase + (kc & 1)*BUF_H*2;
        gemm_mma_chunk(sb, sb + 128*SK*2, sb + 2*128*SK*2, aoff, boff, acc);
        __syncthreads();
    }

    #pragma unroll
    for (int mt = 0; mt < 4; mt++) {
        int mrow = m0 + wm*64 + mt*16 + (lane >> 2);
        #pragma unroll
        for (int half = 0; half < 2; half++) {
            int m = mrow + half*8;
            #pragma unroll
            for (int nt = 0; nt < 4; nt++) {
                int n = wn*32 + nt*8 + ((lane & 3) << 1);
                float c0 = acc[mt][nt][half*2+0] + bp[n0 + n];
                float c1 = acc[mt][nt][half*2+1] + bp[n0 + n + 1];
                *(float2*)&outp[(size_t)m*C_ + n0 + n] = make_float2(c0, c1);
            }
        }
    }
}

// ---------------------------------------------------------------------------
extern "C" void kernel_launch(void* const* d_in, const int* in_sizes, int n_in,
                              void* d_out, int out_size)
{
    const float* x  = (const float*)d_in[0];
    const float* Wq = (const float*)d_in[1];
    const float* bq = (const float*)d_in[2];
    const float* Wk = (const float*)d_in[3];
    const float* bk = (const float*)d_in[4];
    const float* Wv = (const float*)d_in[5];
    const float* bv = (const float*)d_in[6];
    const float* Wp = (const float*)d_in[7];
    const float* bp = (const float*)d_in[8];
    float* out = (float*)d_out;

    cudaFuncSetAttribute(qkv_mma,  cudaFuncAttributeMaxDynamicSharedMemorySize, GEMM_SMEM);
    cudaFuncSetAttribute(proj_mma, cudaFuncAttributeMaxDynamicSharedMemorySize, GEMM_SMEM);

    qkv_mma<<<dim3(64, 24), 256, GEMM_SMEM>>>(x, Wq, bq, Wk, bk, Wv, bv);
    attn_mma<<<dim3(16, 64), 256>>>();
    proj_mma<<<dim3(64, 8), 256, GEMM_SMEM>>>(Wp, bp, out);
}

// round 9
// speedup vs baseline: 3.9464x; 1.0150x over previous
#include <cuda_runtime.h>
#include <cuda_fp16.h>
#include <math.h>
#include <stdint.h>

#define B_  4
#define T_  2048
#define C_  1024
#define H_  16
#define HD_ 64
#define M_  (B_*T_)   // 8192

// fp16 scratch (allocation-free)
__device__ __half g_xh[M_*C_], g_xl[M_*C_];
__device__ __half g_wqT[H_*HD_*C_], g_wkT[H_*HD_*C_], g_wvT[H_*HD_*C_];
__device__ __half g_wpT[C_*C_];
__device__ __half g_qh[M_*C_], g_ql[M_*C_];
__device__ __half g_kh[M_*C_], g_vh[M_*C_];
__device__ __half g_oh[M_*C_], g_ol[M_*C_];
__device__ float  g_bias[3*H_*HD_];

// ---------------------------------------------------------------------------
// helpers
// ---------------------------------------------------------------------------
__device__ __forceinline__ uint32_t smem_u32(const void* p){
    uint32_t a;
    asm("{ .reg .u64 t; cvta.to.shared.u64 t, %1; cvt.u32.u64 %0, t; }"
        : "=r"(a) : "l"(p));
    return a;
}
__device__ __forceinline__ void ldsm_x4(uint32_t* r, uint32_t addr){
    asm volatile("ldmatrix.sync.aligned.m8n8.x4.shared.b16 {%0,%1,%2,%3}, [%4];"
        : "=r"(r[0]), "=r"(r[1]), "=r"(r[2]), "=r"(r[3]) : "r"(addr));
}
__device__ __forceinline__ void ldsm_x2(uint32_t* r, uint32_t addr){
    asm volatile("ldmatrix.sync.aligned.m8n8.x2.shared.b16 {%0,%1}, [%2];"
        : "=r"(r[0]), "=r"(r[1]) : "r"(addr));
}
__device__ __forceinline__ void ldsm_x2t(uint32_t* r, uint32_t addr){
    asm volatile("ldmatrix.sync.aligned.m8n8.x2.trans.shared.b16 {%0,%1}, [%2];"
        : "=r"(r[0]), "=r"(r[1]) : "r"(addr));
}
__device__ __forceinline__ void mma16816(float* c, const uint32_t* a, const uint32_t* b){
    asm volatile(
        "mma.sync.aligned.m16n8k16.row.col.f32.f16.f16.f32 "
        "{%0,%1,%2,%3}, {%4,%5,%6,%7}, {%8,%9}, {%0,%1,%2,%3};"
        : "+f"(c[0]), "+f"(c[1]), "+f"(c[2]), "+f"(c[3])
        : "r"(a[0]), "r"(a[1]), "r"(a[2]), "r"(a[3]), "r"(b[0]), "r"(b[1]));
}
__device__ __forceinline__ void cp16(uint32_t dst, const void* src){
    asm volatile("cp.async.cg.shared.global [%0], [%1], 16;" :: "r"(dst), "l"(src));
}
#define CP_COMMIT() asm volatile("cp.async.commit_group;" ::: "memory")
#define CP_WAIT1()  asm volatile("cp.async.wait_group 1;" ::: "memory")

__device__ __forceinline__ void pack_hl_h(float a, float b, uint32_t& hi, uint32_t& lo){
    __half2 hp = __floats2half2_rn(a, b);
    hi = *(uint32_t*)&hp;
    __half2 lp = __floats2half2_rn(a - __low2float(hp), b - __high2float(hp));
    lo = *(uint32_t*)&lp;
}

// ---------------------------------------------------------------------------
// Prologue kernels
// ---------------------------------------------------------------------------
__global__ __launch_bounds__(256) void conv_x(const float* __restrict__ x){
    int i = (blockIdx.x*256 + threadIdx.x) * 4;
    float4 a = *(const float4*)(x + i);
    __half2 h0 = __floats2half2_rn(a.x, a.y);
    __half2 h1 = __floats2half2_rn(a.z, a.w);
    __half2 l0 = __floats2half2_rn(a.x - __low2float(h0), a.y - __high2float(h0));
    __half2 l1 = __floats2half2_rn(a.z - __low2float(h1), a.w - __high2float(h1));
    uint2 hi, lo;
    hi.x = *(uint32_t*)&h0; hi.y = *(uint32_t*)&h1;
    lo.x = *(uint32_t*)&l0; lo.y = *(uint32_t*)&l1;
    *(uint2*)&g_xh[i] = hi;
    *(uint2*)&g_xl[i] = lo;
}

__global__ __launch_bounds__(256) void conv_w(
    const float* __restrict__ Wq, const float* __restrict__ Wk,
    const float* __restrict__ Wv, const float* __restrict__ Wp)
{
    int idx = blockIdx.x*256 + threadIdx.x;           // 0 .. 4M-1
    int which = idx >> 20;
    int o = idx & 0xFFFFF;
    if (which < 3) {
        const float* W = (which == 0) ? Wq : (which == 1) ? Wk : Wv;
        __half* wT = (which == 0) ? g_wqT : (which == 1) ? g_wkT : g_wvT;
        int c = o & (C_-1);
        int d = (o >> 10) & 63;
        int h = o >> 16;
        wT[o] = __float2half_rn(W[((size_t)h*C_ + c)*HD_ + d]);
    } else {
        int k = o & (C_-1);
        int n = o >> 10;
        g_wpT[o] = __float2half_rn(Wp[(size_t)k*C_ + n]);
    }
}

__global__ void stage_bias(const float* bq, const float* bk, const float* bv){
    int i = threadIdx.x + blockIdx.x*256;
    if (i < H_*HD_) {
        g_bias[i] = bq[i];
        g_bias[H_*HD_ + i] = bk[i];
        g_bias[2*H_*HD_ + i] = bv[i];
    }
}

// ---------------------------------------------------------------------------
// GEMM mma chunk
// ---------------------------------------------------------------------------
#define SK  40
#define TILE_H (128*SK)
#define STAGE_H (3*TILE_H)
#define GEMM_SMEM (3*STAGE_H*2)   // 92160 B

__device__ __forceinline__ void gemm_mma_chunk(
    uint32_t st, uint32_t aoff, uint32_t boff, float acc[4][4][4])
{
    uint32_t sAh = st, sAl = st + TILE_H*2, sB = st + 2*TILE_H*2;
    uint32_t bf[2][4][2];
    #pragma unroll
    for (int ks = 0; ks < 2; ks++)
        #pragma unroll
        for (int nt = 0; nt < 4; nt++)
            ldsm_x2(bf[ks][nt], sB + boff + (nt*8*SK + ks*16)*2);

    #pragma unroll
    for (int pass = 0; pass < 2; pass++) {
        uint32_t sA = pass ? sAl : sAh;
        #pragma unroll
        for (int ks = 0; ks < 2; ks++) {
            uint32_t af[4][4];
            #pragma unroll
            for (int mt = 0; mt < 4; mt++)
                ldsm_x4(af[mt], sA + aoff + (mt*16*SK + ks*16)*2);
            #pragma unroll
            for (int mt = 0; mt < 4; mt++)
                #pragma unroll
                for (int nt = 0; nt < 4; nt++)
                    mma16816(acc[mt][nt], af[mt], bf[ks][nt]);
        }
    }
}

// ---------------------------------------------------------------------------
// Kernel 1: QKV projection
// ---------------------------------------------------------------------------
__global__ __launch_bounds__(256) void qkv_mma()
{
    extern __shared__ __half dynsm[];
    int tid = threadIdx.x, wid = tid >> 5, lane = tid & 31;
    int wm = wid >> 2, wn = wid & 3;
    int mt_ = blockIdx.x, nt_ = blockIdx.y;
    int which = nt_ >> 3, hbase = (nt_ & 7) * 2;
    const int m0 = mt_ * 128;

    const __half* wT = (which == 0) ? g_wqT : (which == 1) ? g_wkT : g_wvT;
    uint32_t sbase = smem_u32(dynsm);
    uint32_t aoff = ((wm*64 + (lane & 15)) * SK + ((lane >> 4) << 3)) * 2;
    uint32_t boff = ((wn*32 + (lane & 7)) * SK + (((lane >> 3) & 1) << 3)) * 2;

    float acc[4][4][4] = {};

    auto fill = [&](int stage, int kc) {
        uint32_t st = sbase + stage*STAGE_H*2;
        int k0 = kc * 32;
        #pragma unroll
        for (int it = 0; it < 6; it++) {
            int part = it >> 1;
            int idx = ((it & 1) << 8) + tid;
            int row = idx >> 2, seg = (idx & 3) << 3;
            if (part == 0) {
                cp16(st + (row*SK + seg)*2,
                     g_xh + (size_t)(m0 + row)*C_ + k0 + seg);
            } else if (part == 1) {
                cp16(st + (TILE_H + row*SK + seg)*2,
                     g_xl + (size_t)(m0 + row)*C_ + k0 + seg);
            } else {
                int h = hbase + (row >> 6), d = row & 63;
                cp16(st + (2*TILE_H + row*SK + seg)*2,
                     wT + ((size_t)h*HD_ + d)*C_ + k0 + seg);
            }
        }
    };

    fill(0, 0); CP_COMMIT();
    fill(1, 1); CP_COMMIT();

    for (int kc = 0; kc < 32; kc++) {
        CP_WAIT1();
        __syncthreads();
        if (kc + 2 < 32) fill((kc + 2) % 3, kc + 2);
        CP_COMMIT();
        gemm_mma_chunk(sbase + (kc % 3)*STAGE_H*2, aoff, boff, acc);
    }

    #pragma unroll
    for (int mt = 0; mt < 4; mt++) {
        int mrow = m0 + wm*64 + mt*16 + (lane >> 2);
        #pragma unroll
        for (int half = 0; half < 2; half++) {
            int m = mrow + half*8;
            int b_ = m >> 11, t = m & (T_-1);
            #pragma unroll
            for (int nt = 0; nt < 4; nt++) {
                int n = wn*32 + nt*8 + ((lane & 3) << 1);
                int h = hbase + (n >> 6), d = n & 63;
                size_t off = (((size_t)(b_*H_ + h))*T_ + t)*HD_ + d;
                float c0 = acc[mt][nt][half*2+0] + g_bias[(which*H_ + h)*HD_ + d];
                float c1 = acc[mt][nt][half*2+1] + g_bias[(which*H_ + h)*HD_ + d + 1];
                if (which == 0) {
                    uint32_t hi, lo; pack_hl_h(c0, c1, hi, lo);
                    *(uint32_t*)&g_qh[off] = hi;
                    *(uint32_t*)&g_ql[off] = lo;
                } else {
                    __half2 p = __floats2half2_rn(c0, c1);
                    if (which == 1) *(uint32_t*)&g_kh[off] = *(uint32_t*)&p;
                    else            *(uint32_t*)&g_vh[off] = *(uint32_t*)&p;
                }
            }
        }
    }
}

// ---------------------------------------------------------------------------
// Kernel 2: attention
// ---------------------------------------------------------------------------
#define SKA 72
#define ATILE_H (64*SKA)
#define ASTAGE_H (2*ATILE_H)
#define ATTN_SMEM (3*ASTAGE_H*2)   // 55296 B

__global__ __launch_bounds__(256) void attn_mma()
{
    extern __shared__ __half asm_[];
    int tid = threadIdx.x, wid = tid >> 5, lane = tid & 31;
    int qt = 15 - blockIdx.x;
    int bh = blockIdx.y;
    const __half* Qh = g_qh + (size_t)bh * T_ * HD_;
    const __half* Ql = g_ql + (size_t)bh * T_ * HD_;
    const __half* Kh = g_kh + (size_t)bh * T_ * HD_;
    const __half* Vh = g_vh + (size_t)bh * T_ * HD_;

    uint32_t sbase = smem_u32(asm_);
    int r0 = lane >> 2, c0 = (lane & 3) << 1;
    int wrow = qt*128 + wid*16;
    int row0 = wrow + r0;

    uint32_t qh[4][4], ql[4][4];
    #pragma unroll
    for (int ks = 0; ks < 4; ks++) {
        #pragma unroll
        for (int p = 0; p < 4; p++) {
            int rr = row0 + ((p & 1) << 3);
            int cc = ks*16 + c0 + ((p >> 1) << 3);
            qh[ks][p] = *(const uint32_t*)&Qh[(size_t)rr*HD_ + cc];
            ql[ks][p] = *(const uint32_t*)&Ql[(size_t)rr*HD_ + cc];
        }
    }

    float o[8][4];
    #pragma unroll
    for (int i = 0; i < 8; i++) { o[i][0]=o[i][1]=o[i][2]=o[i][3]=0.f; }
    float m_i[2] = {-1e30f, -1e30f}, l_i[2] = {0.f, 0.f};
    int jmax = 2*qt + 1;

    auto fill = [&](int stage, int j) {
        uint32_t st = sbase + stage*ASTAGE_H*2;
        int s0 = j * 64;
        #pragma unroll
        for (int it = 0; it < 4; it++) {
            int part = it >> 1;
            int idx = ((it & 1) << 8) + tid;
            int row = idx >> 3, seg = (idx & 7) << 3;
            if (part == 0)
                cp16(st + (row*SKA + seg)*2, Kh + (size_t)(s0 + row)*HD_ + seg);
            else
                cp16(st + (ATILE_H + row*SKA + seg)*2, Vh + (size_t)(s0 + row)*HD_ + seg);
        }
    };

    fill(0, 0); CP_COMMIT();
    fill(1, 1); CP_COMMIT();

    for (int j = 0; j <= jmax; j++) {
        CP_WAIT1();
        __syncthreads();
        if (j + 2 <= jmax) fill((j + 2) % 3, j + 2);
        CP_COMMIT();

        bool dead = (j*64) > (wrow + 15);
        if (!dead) {
            uint32_t st = sbase + (j % 3)*ASTAGE_H*2;
            uint32_t sK = st, sV = st + ATILE_H*2;
            float c[8][4] = {};
            #pragma unroll
            for (int ks = 0; ks < 4; ks++) {
                uint32_t bf[8][2];
                #pragma unroll
                for (int nt = 0; nt < 8; nt++) {
                    uint32_t off = ((nt*8 + (lane & 7))*SKA + ks*16 + ((lane >> 3) & 1)*8) * 2;
                    ldsm_x2(bf[nt], sK + off);
                }
                #pragma unroll
                for (int nt = 0; nt < 8; nt++) {
                    mma16816(c[nt], qh[ks], bf[nt]);
                    mma16816(c[nt], ql[ks], bf[nt]);
                }
            }
            bool dflag = (j >= 2*qt);
            #pragma unroll
            for (int nt = 0; nt < 8; nt++) {
                #pragma unroll
                for (int e = 0; e < 4; e++) {
                    float s = c[nt][e] * 0.03125f;
                    if (dflag) {
                        int col = j*64 + nt*8 + c0 + (e & 1);
                        int row = row0 + ((e >> 1) << 3);
                        if (col > row) s = -1e30f;
                    }
                    c[nt][e] = s;
                }
            }
            #pragma unroll
            for (int r = 0; r < 2; r++) {
                float mx = -1e30f;
                #pragma unroll
                for (int nt = 0; nt < 8; nt++)
                    mx = fmaxf(mx, fmaxf(c[nt][2*r], c[nt][2*r+1]));
                mx = fmaxf(mx, __shfl_xor_sync(0xffffffffu, mx, 1));
                mx = fmaxf(mx, __shfl_xor_sync(0xffffffffu, mx, 2));
                float mnew = fmaxf(m_i[r], mx);
                float alpha = __expf(m_i[r] - mnew);
                m_i[r] = mnew;
                float rs = 0.f;
                #pragma unroll
                for (int nt = 0; nt < 8; nt++) {
                    float p0 = __expf(c[nt][2*r]   - mnew);
                    float p1 = __expf(c[nt][2*r+1] - mnew);
                    c[nt][2*r] = p0; c[nt][2*r+1] = p1;
                    rs += p0 + p1;
                }
                rs += __shfl_xor_sync(0xffffffffu, rs, 1);
                rs += __shfl_xor_sync(0xffffffffu, rs, 2);
                l_i[r] = l_i[r]*alpha + rs;
                #pragma unroll
                for (int nt = 0; nt < 8; nt++) {
                    o[nt][2*r]   *= alpha;
                    o[nt][2*r+1] *= alpha;
                }
            }
            #pragma unroll
            for (int ks = 0; ks < 4; ks++) {
                uint32_t ph[4], pl[4];
                pack_hl_h(c[2*ks][0],   c[2*ks][1],   ph[0], pl[0]);
                pack_hl_h(c[2*ks][2],   c[2*ks][3],   ph[1], pl[1]);
                pack_hl_h(c[2*ks+1][0], c[2*ks+1][1], ph[2], pl[2]);
                pack_hl_h(c[2*ks+1][2], c[2*ks+1][3], ph[3], pl[3]);
                uint32_t bv[8][2];
                #pragma unroll
                for (int nt = 0; nt < 8; nt++) {
                    uint32_t off = ((ks*16 + (lane & 7) + ((lane >> 3) & 1)*8)*SKA + nt*8) * 2;
                    ldsm_x2t(bv[nt], sV + off);
                }
                #pragma unroll
                for (int nt = 0; nt < 8; nt++) {
                    mma16816(o[nt], ph, bv[nt]);
                    mma16816(o[nt], pl, bv[nt]);
                }
            }
        }
        __syncthreads();
    }

    float inv0 = 1.0f / l_i[0], inv1 = 1.0f / l_i[1];
    __half* Oh = g_oh + (size_t)bh * T_ * HD_;
    __half* Ol = g_ol + (size_t)bh * T_ * HD_;
    #pragma unroll
    for (int nt = 0; nt < 8; nt++) {
        int d = nt*8 + c0;
        uint32_t hi, lo;
        pack_hl_h(o[nt][0]*inv0, o[nt][1]*inv0, hi, lo);
        *(uint32_t*)&Oh[(size_t)row0*HD_ + d] = hi;
        *(uint32_t*)&Ol[(size_t)row0*HD_ + d] = lo;
        pack_hl_h(o[nt][2]*inv1, o[nt][3]*inv1, hi, lo);
        *(uint32_t*)&Oh[(size_t)(row0+8)*HD_ + d] = hi;
        *(uint32_t*)&Ol[(size_t)(row0+8)*HD_ + d] = lo;
    }
}

// ---------------------------------------------------------------------------
// Kernel 3: output projection
// ---------------------------------------------------------------------------
__global__ __launch_bounds__(256) void proj_mma(
    const float* __restrict__ bp, float* __restrict__ outp)
{
    extern __shared__ __half dynsm[];
    int tid = threadIdx.x, wid = tid >> 5, lane = tid & 31;
    int wm = wid >> 2, wn = wid & 3;
    const int m0 = blockIdx.x * 128, n0 = blockIdx.y * 128;

    uint32_t sbase = smem_u32(dynsm);
    uint32_t aoff = ((wm*64 + (lane & 15)) * SK + ((lane >> 4) << 3)) * 2;
    uint32_t boff = ((wn*32 + (lane & 7)) * SK + (((lane >> 3) & 1) << 3)) * 2;

    float acc[4][4][4] = {};

    auto fill = [&](int stage, int kc) {
        uint32_t st = sbase + stage*STAGE_H*2;
        int k0 = kc * 32;
        int h = k0 >> 6, dl = k0 & 63;
        #pragma unroll
        for (int it = 0; it < 6; it++) {
            int part = it >> 1;
            int idx = ((it & 1) << 8) + tid;
            int row = idx >> 2, seg = (idx & 3) << 3;
            if (part < 2) {
                int m = m0 + row, b_ = m >> 11, t = m & (T_-1);
                const __half* src = (part == 0 ? g_oh : g_ol) +
                    (((size_t)(b_*H_ + h))*T_ + t)*HD_ + dl + seg;
                cp16(st + (part*TILE_H + row*SK + seg)*2, src);
            } else {
                cp16(st + (2*TILE_H + row*SK + seg)*2,
                     g_wpT + (size_t)(n0 + row)*C_ + k0 + seg);
            }
        }
    };

    fill(0, 0); CP_COMMIT();
    fill(1, 1); CP_COMMIT();

    for (int kc = 0; kc < 32; kc++) {
        CP_WAIT1();
        __syncthreads();
        if (kc + 2 < 32) fill((kc + 2) % 3, kc + 2);
        CP_COMMIT();
        gemm_mma_chunk(sbase + (kc % 3)*STAGE_H*2, aoff, boff, acc);
    }

    #pragma unroll
    for (int mt = 0; mt < 4; mt++) {
        int mrow = m0 + wm*64 + mt*16 + (lane >> 2);
        #pragma unroll
        for (int half = 0; half < 2; half++) {
            int m = mrow + half*8;
            #pragma unroll
            for (int nt = 0; nt < 4; nt++) {
                int n = wn*32 + nt*8 + ((lane & 3) << 1);
                float c0 = acc[mt][nt][half*2+0] + bp[n0 + n];
                float c1 = acc[mt][nt][half*2+1] + bp[n0 + n + 1];
                *(float2*)&outp[(size_t)m*C_ + n0 + n] = make_float2(c0, c1);
            }
        }
    }
}

// ---------------------------------------------------------------------------
extern "C" void kernel_launch(void* const* d_in, const int* in_sizes, int n_in,
                              void* d_out, int out_size)
{
    const float* x  = (const float*)d_in[0];
    const float* Wq = (const float*)d_in[1];
    const float* bq = (const float*)d_in[2];
    const float* Wk = (const float*)d_in[3];
    const float* bk = (const float*)d_in[4];
    const float* Wv = (const float*)d_in[5];
    const float* bv = (const float*)d_in[6];
    const float* Wp = (const float*)d_in[7];
    const float* bp = (const float*)d_in[8];
    float* out = (float*)d_out;

    cudaFuncSetAttribute(qkv_mma,  cudaFuncAttributeMaxDynamicSharedMemorySize, GEMM_SMEM);
    cudaFuncSetAttribute(proj_mma, cudaFuncAttributeMaxDynamicSharedMemorySize, GEMM_SMEM);
    cudaFuncSetAttribute(attn_mma, cudaFuncAttributeMaxDynamicSharedMemorySize, ATTN_SMEM);

    conv_x<<<M_*C_/4/256, 256>>>(x);
    conv_w<<<4*1048576/256, 256>>>(Wq, Wk, Wv, Wp);
    stage_bias<<<4, 256>>>(bq, bk, bv);
    qkv_mma<<<dim3(64, 24), 256, GEMM_SMEM>>>();
    attn_mma<<<dim3(16, 64), 256, ATTN_SMEM>>>();
    proj_mma<<<dim3(64, 8), 256, GEMM_SMEM>>>(bp, out);
}

// round 10
// speedup vs baseline: 4.8503x; 1.2291x over previous
#include <cuda_runtime.h>
#include <cuda_fp16.h>
#include <math.h>
#include <stdint.h>

#define B_  4
#define T_  2048
#define C_  1024
#define H_  16
#define HD_ 64
#define M_  (B_*T_)   // 8192

// fp16 scratch (allocation-free)
__device__ __half g_xh[M_*C_], g_xl[M_*C_];
__device__ __half g_wqT[H_*HD_*C_], g_wkT[H_*HD_*C_], g_wvT[H_*HD_*C_];
__device__ __half g_wpT[C_*C_];
__device__ __half g_qh[M_*C_], g_ql[M_*C_];
__device__ __half g_kh[M_*C_], g_vh[M_*C_];
__device__ __half g_oh[M_*C_], g_ol[M_*C_];
__device__ float  g_bias[3*H_*HD_];

// ---------------------------------------------------------------------------
// helpers
// ---------------------------------------------------------------------------
__device__ __forceinline__ uint32_t smem_u32(const void* p){
    uint32_t a;
    asm("{ .reg .u64 t; cvta.to.shared.u64 t, %1; cvt.u32.u64 %0, t; }"
        : "=r"(a) : "l"(p));
    return a;
}
__device__ __forceinline__ void ldsm_x4(uint32_t* r, uint32_t addr){
    asm volatile("ldmatrix.sync.aligned.m8n8.x4.shared.b16 {%0,%1,%2,%3}, [%4];"
        : "=r"(r[0]), "=r"(r[1]), "=r"(r[2]), "=r"(r[3]) : "r"(addr));
}
__device__ __forceinline__ void ldsm_x2(uint32_t* r, uint32_t addr){
    asm volatile("ldmatrix.sync.aligned.m8n8.x2.shared.b16 {%0,%1}, [%2];"
        : "=r"(r[0]), "=r"(r[1]) : "r"(addr));
}
__device__ __forceinline__ void ldsm_x2t(uint32_t* r, uint32_t addr){
    asm volatile("ldmatrix.sync.aligned.m8n8.x2.trans.shared.b16 {%0,%1}, [%2];"
        : "=r"(r[0]), "=r"(r[1]) : "r"(addr));
}
__device__ __forceinline__ void mma16816(float* c, const uint32_t* a, const uint32_t* b){
    asm volatile(
        "mma.sync.aligned.m16n8k16.row.col.f32.f16.f16.f32 "
        "{%0,%1,%2,%3}, {%4,%5,%6,%7}, {%8,%9}, {%0,%1,%2,%3};"
        : "+f"(c[0]), "+f"(c[1]), "+f"(c[2]), "+f"(c[3])
        : "r"(a[0]), "r"(a[1]), "r"(a[2]), "r"(a[3]), "r"(b[0]), "r"(b[1]));
}
__device__ __forceinline__ void cp16(uint32_t dst, const void* src){
    asm volatile("cp.async.cg.shared.global [%0], [%1], 16;" :: "r"(dst), "l"(src));
}
#define CP_COMMIT() asm volatile("cp.async.commit_group;" ::: "memory")
#define CP_WAIT1()  asm volatile("cp.async.wait_group 1;" ::: "memory")

__device__ __forceinline__ void pack_hl_h(float a, float b, uint32_t& hi, uint32_t& lo){
    __half2 hp = __floats2half2_rn(a, b);
    hi = *(uint32_t*)&hp;
    __half2 lp = __floats2half2_rn(a - __low2float(hp), b - __high2float(hp));
    lo = *(uint32_t*)&lp;
}
__device__ __forceinline__ uint32_t pack_h(float a, float b){
    __half2 hp = __floats2half2_rn(a, b);
    return *(uint32_t*)&hp;
}

// ---------------------------------------------------------------------------
// Prologue kernels
// ---------------------------------------------------------------------------
__global__ __launch_bounds__(256) void conv_x(const float* __restrict__ x){
    int i = (blockIdx.x*256 + threadIdx.x) * 4;
    float4 a = *(const float4*)(x + i);
    __half2 h0 = __floats2half2_rn(a.x, a.y);
    __half2 h1 = __floats2half2_rn(a.z, a.w);
    __half2 l0 = __floats2half2_rn(a.x - __low2float(h0), a.y - __high2float(h0));
    __half2 l1 = __floats2half2_rn(a.z - __low2float(h1), a.w - __high2float(h1));
    uint2 hi, lo;
    hi.x = *(uint32_t*)&h0; hi.y = *(uint32_t*)&h1;
    lo.x = *(uint32_t*)&l0; lo.y = *(uint32_t*)&l1;
    *(uint2*)&g_xh[i] = hi;
    *(uint2*)&g_xl[i] = lo;
}

__global__ __launch_bounds__(256) void conv_w(
    const float* __restrict__ Wq, const float* __restrict__ Wk,
    const float* __restrict__ Wv, const float* __restrict__ Wp)
{
    int idx = blockIdx.x*256 + threadIdx.x;           // 0 .. 4M-1
    int which = idx >> 20;
    int o = idx & 0xFFFFF;
    if (which < 3) {
        const float* W = (which == 0) ? Wq : (which == 1) ? Wk : Wv;
        __half* wT = (which == 0) ? g_wqT : (which == 1) ? g_wkT : g_wvT;
        int c = o & (C_-1);
        int d = (o >> 10) & 63;
        int h = o >> 16;
        wT[o] = __float2half_rn(W[((size_t)h*C_ + c)*HD_ + d]);
    } else {
        int k = o & (C_-1);
        int n = o >> 10;
        g_wpT[o] = __float2half_rn(Wp[(size_t)k*C_ + n]);
    }
}

__global__ void stage_bias(const float* bq, const float* bk, const float* bv){
    int i = threadIdx.x + blockIdx.x*256;
    if (i < H_*HD_) {
        g_bias[i] = bq[i];
        g_bias[H_*HD_ + i] = bk[i];
        g_bias[2*H_*HD_ + i] = bv[i];
    }
}

// ---------------------------------------------------------------------------
// GEMM mma chunk (npass = 1: hi only; 2: hi+lo A-passes)
// ---------------------------------------------------------------------------
#define SK  40
#define TILE_H (128*SK)
#define STAGE_H (3*TILE_H)
#define GEMM_SMEM (3*STAGE_H*2)   // 92160 B

__device__ __forceinline__ void gemm_mma_chunk(
    uint32_t st, uint32_t aoff, uint32_t boff, float acc[4][4][4], int npass)
{
    uint32_t sAh = st, sAl = st + TILE_H*2, sB = st + 2*TILE_H*2;
    uint32_t bf[2][4][2];
    #pragma unroll
    for (int ks = 0; ks < 2; ks++)
        #pragma unroll
        for (int nt = 0; nt < 4; nt++)
            ldsm_x2(bf[ks][nt], sB + boff + (nt*8*SK + ks*16)*2);

    #pragma unroll
    for (int pass = 0; pass < 2; pass++) {
        if (pass == 1 && npass == 1) break;
        uint32_t sA = pass ? sAl : sAh;
        #pragma unroll
        for (int ks = 0; ks < 2; ks++) {
            uint32_t af[4][4];
            #pragma unroll
            for (int mt = 0; mt < 4; mt++)
                ldsm_x4(af[mt], sA + aoff + (mt*16*SK + ks*16)*2);
            #pragma unroll
            for (int mt = 0; mt < 4; mt++)
                #pragma unroll
                for (int nt = 0; nt < 4; nt++)
                    mma16816(acc[mt][nt], af[mt], bf[ks][nt]);
        }
    }
}

// ---------------------------------------------------------------------------
// Kernel 1: QKV projection. Q: 2-pass (x hi+lo). K,V: 1-pass (x hi only).
// ---------------------------------------------------------------------------
__global__ __launch_bounds__(256) void qkv_mma()
{
    extern __shared__ __half dynsm[];
    int tid = threadIdx.x, wid = tid >> 5, lane = tid & 31;
    int wm = wid >> 2, wn = wid & 3;
    int mt_ = blockIdx.x, nt_ = blockIdx.y;
    int which = nt_ >> 3, hbase = (nt_ & 7) * 2;
    const int m0 = mt_ * 128;
    const int npass = (which == 0) ? 2 : 1;

    const __half* wT = (which == 0) ? g_wqT : (which == 1) ? g_wkT : g_wvT;
    uint32_t sbase = smem_u32(dynsm);
    uint32_t aoff = ((wm*64 + (lane & 15)) * SK + ((lane >> 4) << 3)) * 2;
    uint32_t boff = ((wn*32 + (lane & 7)) * SK + (((lane >> 3) & 1) << 3)) * 2;

    float acc[4][4][4] = {};

    auto fill = [&](int stage, int kc) {
        uint32_t st = sbase + stage*STAGE_H*2;
        int k0 = kc * 32;
        #pragma unroll
        for (int it = 0; it < 6; it++) {
            int part = it >> 1;
            int idx = ((it & 1) << 8) + tid;
            int row = idx >> 2, seg = (idx & 3) << 3;
            if (part == 0) {
                cp16(st + (row*SK + seg)*2,
                     g_xh + (size_t)(m0 + row)*C_ + k0 + seg);
            } else if (part == 1) {
                if (npass == 2)
                    cp16(st + (TILE_H + row*SK + seg)*2,
                         g_xl + (size_t)(m0 + row)*C_ + k0 + seg);
            } else {
                int h = hbase + (row >> 6), d = row & 63;
                cp16(st + (2*TILE_H + row*SK + seg)*2,
                     wT + ((size_t)h*HD_ + d)*C_ + k0 + seg);
            }
        }
    };

    fill(0, 0); CP_COMMIT();
    fill(1, 1); CP_COMMIT();

    for (int kc = 0; kc < 32; kc++) {
        CP_WAIT1();
        __syncthreads();
        if (kc + 2 < 32) fill((kc + 2) % 3, kc + 2);
        CP_COMMIT();
        gemm_mma_chunk(sbase + (kc % 3)*STAGE_H*2, aoff, boff, acc, npass);
    }

    #pragma unroll
    for (int mt = 0; mt < 4; mt++) {
        int mrow = m0 + wm*64 + mt*16 + (lane >> 2);
        #pragma unroll
        for (int half = 0; half < 2; half++) {
            int m = mrow + half*8;
            int b_ = m >> 11, t = m & (T_-1);
            #pragma unroll
            for (int nt = 0; nt < 4; nt++) {
                int n = wn*32 + nt*8 + ((lane & 3) << 1);
                int h = hbase + (n >> 6), d = n & 63;
                size_t off = (((size_t)(b_*H_ + h))*T_ + t)*HD_ + d;
                float c0 = acc[mt][nt][half*2+0] + g_bias[(which*H_ + h)*HD_ + d];
                float c1 = acc[mt][nt][half*2+1] + g_bias[(which*H_ + h)*HD_ + d + 1];
                if (which == 0) {
                    uint32_t hi, lo; pack_hl_h(c0, c1, hi, lo);
                    *(uint32_t*)&g_qh[off] = hi;
                    *(uint32_t*)&g_ql[off] = lo;
                } else {
                    uint32_t p = pack_h(c0, c1);
                    if (which == 1) *(uint32_t*)&g_kh[off] = p;
                    else            *(uint32_t*)&g_vh[off] = p;
                }
            }
        }
    }
}

// ---------------------------------------------------------------------------
// Kernel 2: attention. S: 2-pass (Q hi/lo). PV: 1-pass (P hi only).
// ---------------------------------------------------------------------------
#define SKA 72
#define ATILE_H (64*SKA)
#define ASTAGE_H (2*ATILE_H)
#define ATTN_SMEM (3*ASTAGE_H*2)   // 55296 B

__global__ __launch_bounds__(256) void attn_mma()
{
    extern __shared__ __half asm_[];
    int tid = threadIdx.x, wid = tid >> 5, lane = tid & 31;
    int qt = 15 - blockIdx.x;
    int bh = blockIdx.y;
    const __half* Qh = g_qh + (size_t)bh * T_ * HD_;
    const __half* Ql = g_ql + (size_t)bh * T_ * HD_;
    const __half* Kh = g_kh + (size_t)bh * T_ * HD_;
    const __half* Vh = g_vh + (size_t)bh * T_ * HD_;

    uint32_t sbase = smem_u32(asm_);
    int r0 = lane >> 2, c0 = (lane & 3) << 1;
    int wrow = qt*128 + wid*16;
    int row0 = wrow + r0;

    uint32_t qh[4][4], ql[4][4];
    #pragma unroll
    for (int ks = 0; ks < 4; ks++) {
        #pragma unroll
        for (int p = 0; p < 4; p++) {
            int rr = row0 + ((p & 1) << 3);
            int cc = ks*16 + c0 + ((p >> 1) << 3);
            qh[ks][p] = *(const uint32_t*)&Qh[(size_t)rr*HD_ + cc];
            ql[ks][p] = *(const uint32_t*)&Ql[(size_t)rr*HD_ + cc];
        }
    }

    float o[8][4];
    #pragma unroll
    for (int i = 0; i < 8; i++) { o[i][0]=o[i][1]=o[i][2]=o[i][3]=0.f; }
    float m_i[2] = {-1e30f, -1e30f}, l_i[2] = {0.f, 0.f};
    int jmax = 2*qt + 1;

    auto fill = [&](int stage, int j) {
        uint32_t st = sbase + stage*ASTAGE_H*2;
        int s0 = j * 64;
        #pragma unroll
        for (int it = 0; it < 4; it++) {
            int part = it >> 1;
            int idx = ((it & 1) << 8) + tid;
            int row = idx >> 3, seg = (idx & 7) << 3;
            if (part == 0)
                cp16(st + (row*SKA + seg)*2, Kh + (size_t)(s0 + row)*HD_ + seg);
            else
                cp16(st + (ATILE_H + row*SKA + seg)*2, Vh + (size_t)(s0 + row)*HD_ + seg);
        }
    };

    fill(0, 0); CP_COMMIT();
    fill(1, 1); CP_COMMIT();

    for (int j = 0; j <= jmax; j++) {
        CP_WAIT1();
        __syncthreads();
        if (j + 2 <= jmax) fill((j + 2) % 3, j + 2);
        CP_COMMIT();

        bool dead = (j*64) > (wrow + 15);
        if (!dead) {
            uint32_t st = sbase + (j % 3)*ASTAGE_H*2;
            uint32_t sK = st, sV = st + ATILE_H*2;
            float c[8][4] = {};
            #pragma unroll
            for (int ks = 0; ks < 4; ks++) {
                uint32_t bf[8][2];
                #pragma unroll
                for (int nt = 0; nt < 8; nt++) {
                    uint32_t off = ((nt*8 + (lane & 7))*SKA + ks*16 + ((lane >> 3) & 1)*8) * 2;
                    ldsm_x2(bf[nt], sK + off);
                }
                #pragma unroll
                for (int nt = 0; nt < 8; nt++) {
                    mma16816(c[nt], qh[ks], bf[nt]);
                    mma16816(c[nt], ql[ks], bf[nt]);
                }
            }
            bool dflag = (j >= 2*qt);
            #pragma unroll
            for (int nt = 0; nt < 8; nt++) {
                #pragma unroll
                for (int e = 0; e < 4; e++) {
                    float s = c[nt][e] * 0.03125f;
                    if (dflag) {
                        int col = j*64 + nt*8 + c0 + (e & 1);
                        int row = row0 + ((e >> 1) << 3);
                        if (col > row) s = -1e30f;
                    }
                    c[nt][e] = s;
                }
            }
            #pragma unroll
            for (int r = 0; r < 2; r++) {
                float mx = -1e30f;
                #pragma unroll
                for (int nt = 0; nt < 8; nt++)
                    mx = fmaxf(mx, fmaxf(c[nt][2*r], c[nt][2*r+1]));
                mx = fmaxf(mx, __shfl_xor_sync(0xffffffffu, mx, 1));
                mx = fmaxf(mx, __shfl_xor_sync(0xffffffffu, mx, 2));
                float mnew = fmaxf(m_i[r], mx);
                float alpha = __expf(m_i[r] - mnew);
                m_i[r] = mnew;
                float rs = 0.f;
                #pragma unroll
                for (int nt = 0; nt < 8; nt++) {
                    float p0 = __expf(c[nt][2*r]   - mnew);
                    float p1 = __expf(c[nt][2*r+1] - mnew);
                    c[nt][2*r] = p0; c[nt][2*r+1] = p1;
                    rs += p0 + p1;
                }
                rs += __shfl_xor_sync(0xffffffffu, rs, 1);
                rs += __shfl_xor_sync(0xffffffffu, rs, 2);
                l_i[r] = l_i[r]*alpha + rs;
                #pragma unroll
                for (int nt = 0; nt < 8; nt++) {
                    o[nt][2*r]   *= alpha;
                    o[nt][2*r+1] *= alpha;
                }
            }
            // O += P V  (1-pass: P hi only)
            #pragma unroll
            for (int ks = 0; ks < 4; ks++) {
                uint32_t ph[4];
                ph[0] = pack_h(c[2*ks][0],   c[2*ks][1]);
                ph[1] = pack_h(c[2*ks][2],   c[2*ks][3]);
                ph[2] = pack_h(c[2*ks+1][0], c[2*ks+1][1]);
                ph[3] = pack_h(c[2*ks+1][2], c[2*ks+1][3]);
                uint32_t bv[8][2];
                #pragma unroll
                for (int nt = 0; nt < 8; nt++) {
                    uint32_t off = ((ks*16 + (lane & 7) + ((lane >> 3) & 1)*8)*SKA + nt*8) * 2;
                    ldsm_x2t(bv[nt], sV + off);
                }
                #pragma unroll
                for (int nt = 0; nt < 8; nt++)
                    mma16816(o[nt], ph, bv[nt]);
            }
        }
        __syncthreads();
    }

    float inv0 = 1.0f / l_i[0], inv1 = 1.0f / l_i[1];
    __half* Oh = g_oh + (size_t)bh * T_ * HD_;
    __half* Ol = g_ol + (size_t)bh * T_ * HD_;
    #pragma unroll
    for (int nt = 0; nt < 8; nt++) {
        int d = nt*8 + c0;
        uint32_t hi, lo;
        pack_hl_h(o[nt][0]*inv0, o[nt][1]*inv0, hi, lo);
        *(uint32_t*)&Oh[(size_t)row0*HD_ + d] = hi;
        *(uint32_t*)&Ol[(size_t)row0*HD_ + d] = lo;
        pack_hl_h(o[nt][2]*inv1, o[nt][3]*inv1, hi, lo);
        *(uint32_t*)&Oh[(size_t)(row0+8)*HD_ + d] = hi;
        *(uint32_t*)&Ol[(size_t)(row0+8)*HD_ + d] = lo;
    }
}

// ---------------------------------------------------------------------------
// Kernel 3: output projection (O hi/lo 2-pass).
// ---------------------------------------------------------------------------
__global__ __launch_bounds__(256) void proj_mma(
    const float* __restrict__ bp, float* __restrict__ outp)
{
    extern __shared__ __half dynsm[];
    int tid = threadIdx.x, wid = tid >> 5, lane = tid & 31;
    int wm = wid >> 2, wn = wid & 3;
    const int m0 = blockIdx.x * 128, n0 = blockIdx.y * 128;

    uint32_t sbase = smem_u32(dynsm);
    uint32_t aoff = ((wm*64 + (lane & 15)) * SK + ((lane >> 4) << 3)) * 2;
    uint32_t boff = ((wn*32 + (lane & 7)) * SK + (((lane >> 3) & 1) << 3)) * 2;

    float acc[4][4][4] = {};

    auto fill = [&](int stage, int kc) {
        uint32_t st = sbase + stage*STAGE_H*2;
        int k0 = kc * 32;
        int h = k0 >> 6, dl = k0 & 63;
        #pragma unroll
        for (int it = 0; it < 6; it++) {
            int part = it >> 1;
            int idx = ((it & 1) << 8) + tid;
            int row = idx >> 2, seg = (idx & 3) << 3;
            if (part < 2) {
                int m = m0 + row, b_ = m >> 11, t = m & (T_-1);
                const __half* src = (part == 0 ? g_oh : g_ol) +
                    (((size_t)(b_*H_ + h))*T_ + t)*HD_ + dl + seg;
                cp16(st + (part*TILE_H + row*SK + seg)*2, src);
            } else {
                cp16(st + (2*TILE_H + row*SK + seg)*2,
                     g_wpT + (size_t)(n0 + row)*C_ + k0 + seg);
            }
        }
    };

    fill(0, 0); CP_COMMIT();
    fill(1, 1); CP_COMMIT();

    for (int kc = 0; kc < 32; kc++) {
        CP_WAIT1();
        __syncthreads();
        if (kc + 2 < 32) fill((kc + 2) % 3, kc + 2);
        CP_COMMIT();
        gemm_mma_chunk(sbase + (kc % 3)*STAGE_H*2, aoff, boff, acc, 2);
    }

    #pragma unroll
    for (int mt = 0; mt < 4; mt++) {
        int mrow = m0 + wm*64 + mt*16 + (lane >> 2);
        #pragma unroll
        for (int half = 0; half < 2; half++) {
            int m = mrow + half*8;
            #pragma unroll
            for (int nt = 0; nt < 4; nt++) {
                int n = wn*32 + nt*8 + ((lane & 3) << 1);
                float c0 = acc[mt][nt][half*2+0] + bp[n0 + n];
                float c1 = acc[mt][nt][half*2+1] + bp[n0 + n + 1];
                *(float2*)&outp[(size_t)m*C_ + n0 + n] = make_float2(c0, c1);
            }
        }
    }
}

// ---------------------------------------------------------------------------
extern "C" void kernel_launch(void* const* d_in, const int* in_sizes, int n_in,
                              void* d_out, int out_size)
{
    const float* x  = (const float*)d_in[0];
    const float* Wq = (const float*)d_in[1];
    const float* bq = (const float*)d_in[2];
    const float* Wk = (const float*)d_in[3];
    const float* bk = (const float*)d_in[4];
    const float* Wv = (const float*)d_in[5];
    const float* bv = (const float*)d_in[6];
    const float* Wp = (const float*)d_in[7];
    const float* bp = (const float*)d_in[8];
    float* out = (float*)d_out;

    cudaFuncSetAttribute(qkv_mma,  cudaFuncAttributeMaxDynamicSharedMemorySize, GEMM_SMEM);
    cudaFuncSetAttribute(proj_mma, cudaFuncAttributeMaxDynamicSharedMemorySize, GEMM_SMEM);
    cudaFuncSetAttribute(attn_mma, cudaFuncAttributeMaxDynamicSharedMemorySize, ATTN_SMEM);

    conv_x<<<M_*C_/4/256, 256>>>(x);
    conv_w<<<4*1048576/256, 256>>>(Wq, Wk, Wv, Wp);
    stage_bias<<<4, 256>>>(bq, bk, bv);
    qkv_mma<<<dim3(64, 24), 256, GEMM_SMEM>>>();
    attn_mma<<<dim3(16, 64), 256, ATTN_SMEM>>>();
    proj_mma<<<dim3(64, 8), 256, GEMM_SMEM>>>(bp, out);
}

// round 11
// speedup vs baseline: 6.5705x; 1.3547x over previous
#include <cuda_runtime.h>
#include <cuda_fp16.h>
#include <math.h>
#include <stdint.h>

#define B_  4
#define T_  2048
#define C_  1024
#define H_  16
#define HD_ 64
#define M_  (B_*T_)   // 8192

// fp16 scratch (allocation-free)
__device__ __half g_xh[M_*C_];
__device__ __half g_wqT[H_*HD_*C_], g_wkT[H_*HD_*C_], g_wvT[H_*HD_*C_];
__device__ __half g_wpT[C_*C_];
__device__ __half g_qh[M_*C_], g_kh[M_*C_], g_vh[M_*C_];
__device__ __half g_oh[M_*C_];
__device__ float  g_bias[3*H_*HD_];

// ---------------------------------------------------------------------------
// helpers
// ---------------------------------------------------------------------------
__device__ __forceinline__ uint32_t smem_u32(const void* p){
    uint32_t a;
    asm("{ .reg .u64 t; cvta.to.shared.u64 t, %1; cvt.u32.u64 %0, t; }"
        : "=r"(a) : "l"(p));
    return a;
}
__device__ __forceinline__ void ldsm_x4(uint32_t* r, uint32_t addr){
    asm volatile("ldmatrix.sync.aligned.m8n8.x4.shared.b16 {%0,%1,%2,%3}, [%4];"
        : "=r"(r[0]), "=r"(r[1]), "=r"(r[2]), "=r"(r[3]) : "r"(addr));
}
__device__ __forceinline__ void ldsm_x2(uint32_t* r, uint32_t addr){
    asm volatile("ldmatrix.sync.aligned.m8n8.x2.shared.b16 {%0,%1}, [%2];"
        : "=r"(r[0]), "=r"(r[1]) : "r"(addr));
}
__device__ __forceinline__ void ldsm_x2t(uint32_t* r, uint32_t addr){
    asm volatile("ldmatrix.sync.aligned.m8n8.x2.trans.shared.b16 {%0,%1}, [%2];"
        : "=r"(r[0]), "=r"(r[1]) : "r"(addr));
}
__device__ __forceinline__ void mma16816(float* c, const uint32_t* a, const uint32_t* b){
    asm volatile(
        "mma.sync.aligned.m16n8k16.row.col.f32.f16.f16.f32 "
        "{%0,%1,%2,%3}, {%4,%5,%6,%7}, {%8,%9}, {%0,%1,%2,%3};"
        : "+f"(c[0]), "+f"(c[1]), "+f"(c[2]), "+f"(c[3])
        : "r"(a[0]), "r"(a[1]), "r"(a[2]), "r"(a[3]), "r"(b[0]), "r"(b[1]));
}
__device__ __forceinline__ void cp16(uint32_t dst, const void* src){
    asm volatile("cp.async.cg.shared.global [%0], [%1], 16;" :: "r"(dst), "l"(src));
}
#define CP_COMMIT() asm volatile("cp.async.commit_group;" ::: "memory")
#define CP_WAIT1()  asm volatile("cp.async.wait_group 1;" ::: "memory")

__device__ __forceinline__ uint32_t pack_h(float a, float b){
    __half2 hp = __floats2half2_rn(a, b);
    return *(uint32_t*)&hp;
}

// ---------------------------------------------------------------------------
// Prologue kernels
// ---------------------------------------------------------------------------
__global__ __launch_bounds__(256) void conv_x(const float* __restrict__ x){
    int i = (blockIdx.x*256 + threadIdx.x) * 4;
    float4 a = *(const float4*)(x + i);
    uint2 hi;
    hi.x = pack_h(a.x, a.y);
    hi.y = pack_h(a.z, a.w);
    *(uint2*)&g_xh[i] = hi;
}

__global__ __launch_bounds__(256) void conv_w(
    const float* __restrict__ Wq, const float* __restrict__ Wk,
    const float* __restrict__ Wv, const float* __restrict__ Wp)
{
    int idx = blockIdx.x*256 + threadIdx.x;           // 0 .. 4M-1
    int which = idx >> 20;
    int o = idx & 0xFFFFF;
    if (which < 3) {
        const float* W = (which == 0) ? Wq : (which == 1) ? Wk : Wv;
        __half* wT = (which == 0) ? g_wqT : (which == 1) ? g_wkT : g_wvT;
        int c = o & (C_-1);
        int d = (o >> 10) & 63;
        int h = o >> 16;
        wT[o] = __float2half_rn(W[((size_t)h*C_ + c)*HD_ + d]);
    } else {
        int k = o & (C_-1);
        int n = o >> 10;
        g_wpT[o] = __float2half_rn(Wp[(size_t)k*C_ + n]);
    }
}

__global__ void stage_bias(const float* bq, const float* bk, const float* bv){
    int i = threadIdx.x + blockIdx.x*256;
    if (i < H_*HD_) {
        g_bias[i] = bq[i];
        g_bias[H_*HD_ + i] = bk[i];
        g_bias[2*H_*HD_ + i] = bv[i];
    }
}

// ---------------------------------------------------------------------------
// GEMM mma chunk: single fp16 pass. Stage = A tile | B tile.
// ---------------------------------------------------------------------------
#define SK  40
#define TILE_H (128*SK)
#define STAGE_H (2*TILE_H)
#define GEMM_SMEM (3*STAGE_H*2)   // 61440 B

__device__ __forceinline__ void gemm_mma_chunk(
    uint32_t st, uint32_t aoff, uint32_t boff, float acc[4][4][4])
{
    uint32_t sA = st, sB = st + TILE_H*2;
    uint32_t bf[2][4][2];
    #pragma unroll
    for (int ks = 0; ks < 2; ks++)
        #pragma unroll
        for (int nt = 0; nt < 4; nt++)
            ldsm_x2(bf[ks][nt], sB + boff + (nt*8*SK + ks*16)*2);

    #pragma unroll
    for (int ks = 0; ks < 2; ks++) {
        uint32_t af[4][4];
        #pragma unroll
        for (int mt = 0; mt < 4; mt++)
            ldsm_x4(af[mt], sA + aoff + (mt*16*SK + ks*16)*2);
        #pragma unroll
        for (int mt = 0; mt < 4; mt++)
            #pragma unroll
            for (int nt = 0; nt < 4; nt++)
                mma16816(acc[mt][nt], af[mt], bf[ks][nt]);
    }
}

// ---------------------------------------------------------------------------
// Kernel 1: QKV projection — all single-pass fp16.
// ---------------------------------------------------------------------------
__global__ __launch_bounds__(256) void qkv_mma()
{
    extern __shared__ __half dynsm[];
    int tid = threadIdx.x, wid = tid >> 5, lane = tid & 31;
    int wm = wid >> 2, wn = wid & 3;
    int mt_ = blockIdx.x, nt_ = blockIdx.y;
    int which = nt_ >> 3, hbase = (nt_ & 7) * 2;
    const int m0 = mt_ * 128;

    const __half* wT = (which == 0) ? g_wqT : (which == 1) ? g_wkT : g_wvT;
    __half* outp = (which == 0) ? g_qh : (which == 1) ? g_kh : g_vh;
    uint32_t sbase = smem_u32(dynsm);
    uint32_t aoff = ((wm*64 + (lane & 15)) * SK + ((lane >> 4) << 3)) * 2;
    uint32_t boff = ((wn*32 + (lane & 7)) * SK + (((lane >> 3) & 1) << 3)) * 2;

    float acc[4][4][4] = {};

    auto fill = [&](int stage, int kc) {
        uint32_t st = sbase + stage*STAGE_H*2;
        int k0 = kc * 32;
        #pragma unroll
        for (int it = 0; it < 4; it++) {
            int part = it >> 1;
            int idx = ((it & 1) << 8) + tid;
            int row = idx >> 2, seg = (idx & 3) << 3;
            if (part == 0) {
                cp16(st + (row*SK + seg)*2,
                     g_xh + (size_t)(m0 + row)*C_ + k0 + seg);
            } else {
                int h = hbase + (row >> 6), d = row & 63;
                cp16(st + (TILE_H + row*SK + seg)*2,
                     wT + ((size_t)h*HD_ + d)*C_ + k0 + seg);
            }
        }
    };

    fill(0, 0); CP_COMMIT();
    fill(1, 1); CP_COMMIT();

    for (int kc = 0; kc < 32; kc++) {
        CP_WAIT1();
        __syncthreads();
        if (kc + 2 < 32) fill((kc + 2) % 3, kc + 2);
        CP_COMMIT();
        gemm_mma_chunk(sbase + (kc % 3)*STAGE_H*2, aoff, boff, acc);
    }

    #pragma unroll
    for (int mt = 0; mt < 4; mt++) {
        int mrow = m0 + wm*64 + mt*16 + (lane >> 2);
        #pragma unroll
        for (int half = 0; half < 2; half++) {
            int m = mrow + half*8;
            int b_ = m >> 11, t = m & (T_-1);
            #pragma unroll
            for (int nt = 0; nt < 4; nt++) {
                int n = wn*32 + nt*8 + ((lane & 3) << 1);
                int h = hbase + (n >> 6), d = n & 63;
                size_t off = (((size_t)(b_*H_ + h))*T_ + t)*HD_ + d;
                float c0 = acc[mt][nt][half*2+0] + g_bias[(which*H_ + h)*HD_ + d];
                float c1 = acc[mt][nt][half*2+1] + g_bias[(which*H_ + h)*HD_ + d + 1];
                *(uint32_t*)&outp[off] = pack_h(c0, c1);
            }
        }
    }
}

// ---------------------------------------------------------------------------
// Kernel 2: attention — single-pass S and PV.
// ---------------------------------------------------------------------------
#define SKA 72
#define ATILE_H (64*SKA)
#define ASTAGE_H (2*ATILE_H)
#define ATTN_SMEM (3*ASTAGE_H*2)   // 55296 B

__global__ __launch_bounds__(256) void attn_mma()
{
    extern __shared__ __half asm_[];
    int tid = threadIdx.x, wid = tid >> 5, lane = tid & 31;
    int qt = 15 - blockIdx.x;
    int bh = blockIdx.y;
    const __half* Qh = g_qh + (size_t)bh * T_ * HD_;
    const __half* Kh = g_kh + (size_t)bh * T_ * HD_;
    const __half* Vh = g_vh + (size_t)bh * T_ * HD_;

    uint32_t sbase = smem_u32(asm_);
    int r0 = lane >> 2, c0 = (lane & 3) << 1;
    int wrow = qt*128 + wid*16;
    int row0 = wrow + r0;

    uint32_t qh[4][4];
    #pragma unroll
    for (int ks = 0; ks < 4; ks++) {
        #pragma unroll
        for (int p = 0; p < 4; p++) {
            int rr = row0 + ((p & 1) << 3);
            int cc = ks*16 + c0 + ((p >> 1) << 3);
            qh[ks][p] = *(const uint32_t*)&Qh[(size_t)rr*HD_ + cc];
        }
    }

    float o[8][4];
    #pragma unroll
    for (int i = 0; i < 8; i++) { o[i][0]=o[i][1]=o[i][2]=o[i][3]=0.f; }
    float m_i[2] = {-1e30f, -1e30f}, l_i[2] = {0.f, 0.f};
    int jmax = 2*qt + 1;

    auto fill = [&](int stage, int j) {
        uint32_t st = sbase + stage*ASTAGE_H*2;
        int s0 = j * 64;
        #pragma unroll
        for (int it = 0; it < 4; it++) {
            int part = it >> 1;
            int idx = ((it & 1) << 8) + tid;
            int row = idx >> 3, seg = (idx & 7) << 3;
            if (part == 0)
                cp16(st + (row*SKA + seg)*2, Kh + (size_t)(s0 + row)*HD_ + seg);
            else
                cp16(st + (ATILE_H + row*SKA + seg)*2, Vh + (size_t)(s0 + row)*HD_ + seg);
        }
    };

    fill(0, 0); CP_COMMIT();
    fill(1, 1); CP_COMMIT();

    for (int j = 0; j <= jmax; j++) {
        CP_WAIT1();
        __syncthreads();
        if (j + 2 <= jmax) fill((j + 2) % 3, j + 2);
        CP_COMMIT();

        bool dead = (j*64) > (wrow + 15);
        if (!dead) {
            uint32_t st = sbase + (j % 3)*ASTAGE_H*2;
            uint32_t sK = st, sV = st + ATILE_H*2;
            // S = Q K^T (single pass)
            float c[8][4] = {};
            #pragma unroll
            for (int ks = 0; ks < 4; ks++) {
                uint32_t bf[8][2];
                #pragma unroll
                for (int nt = 0; nt < 8; nt++) {
                    uint32_t off = ((nt*8 + (lane & 7))*SKA + ks*16 + ((lane >> 3) & 1)*8) * 2;
                    ldsm_x2(bf[nt], sK + off);
                }
                #pragma unroll
                for (int nt = 0; nt < 8; nt++)
                    mma16816(c[nt], qh[ks], bf[nt]);
            }
            // scale + causal mask
            bool dflag = (j >= 2*qt);
            #pragma unroll
            for (int nt = 0; nt < 8; nt++) {
                #pragma unroll
                for (int e = 0; e < 4; e++) {
                    float s = c[nt][e] * 0.03125f;
                    if (dflag) {
                        int col = j*64 + nt*8 + c0 + (e & 1);
                        int row = row0 + ((e >> 1) << 3);
                        if (col > row) s = -1e30f;
                    }
                    c[nt][e] = s;
                }
            }
            // online softmax
            #pragma unroll
            for (int r = 0; r < 2; r++) {
                float mx = -1e30f;
                #pragma unroll
                for (int nt = 0; nt < 8; nt++)
                    mx = fmaxf(mx, fmaxf(c[nt][2*r], c[nt][2*r+1]));
                mx = fmaxf(mx, __shfl_xor_sync(0xffffffffu, mx, 1));
                mx = fmaxf(mx, __shfl_xor_sync(0xffffffffu, mx, 2));
                float mnew = fmaxf(m_i[r], mx);
                float alpha = __expf(m_i[r] - mnew);
                m_i[r] = mnew;
                float rs = 0.f;
                #pragma unroll
                for (int nt = 0; nt < 8; nt++) {
                    float p0 = __expf(c[nt][2*r]   - mnew);
                    float p1 = __expf(c[nt][2*r+1] - mnew);
                    c[nt][2*r] = p0; c[nt][2*r+1] = p1;
                    rs += p0 + p1;
                }
                rs += __shfl_xor_sync(0xffffffffu, rs, 1);
                rs += __shfl_xor_sync(0xffffffffu, rs, 2);
                l_i[r] = l_i[r]*alpha + rs;
                #pragma unroll
                for (int nt = 0; nt < 8; nt++) {
                    o[nt][2*r]   *= alpha;
                    o[nt][2*r+1] *= alpha;
                }
            }
            // O += P V (single pass)
            #pragma unroll
            for (int ks = 0; ks < 4; ks++) {
                uint32_t ph[4];
                ph[0] = pack_h(c[2*ks][0],   c[2*ks][1]);
                ph[1] = pack_h(c[2*ks][2],   c[2*ks][3]);
                ph[2] = pack_h(c[2*ks+1][0], c[2*ks+1][1]);
                ph[3] = pack_h(c[2*ks+1][2], c[2*ks+1][3]);
                uint32_t bv[8][2];
                #pragma unroll
                for (int nt = 0; nt < 8; nt++) {
                    uint32_t off = ((ks*16 + (lane & 7) + ((lane >> 3) & 1)*8)*SKA + nt*8) * 2;
                    ldsm_x2t(bv[nt], sV + off);
                }
                #pragma unroll
                for (int nt = 0; nt < 8; nt++)
                    mma16816(o[nt], ph, bv[nt]);
            }
        }
        __syncthreads();
    }

    float inv0 = 1.0f / l_i[0], inv1 = 1.0f / l_i[1];
    __half* Oh = g_oh + (size_t)bh * T_ * HD_;
    #pragma unroll
    for (int nt = 0; nt < 8; nt++) {
        int d = nt*8 + c0;
        *(uint32_t*)&Oh[(size_t)row0*HD_ + d]     = pack_h(o[nt][0]*inv0, o[nt][1]*inv0);
        *(uint32_t*)&Oh[(size_t)(row0+8)*HD_ + d] = pack_h(o[nt][2]*inv1, o[nt][3]*inv1);
    }
}

// ---------------------------------------------------------------------------
// Kernel 3: output projection — single-pass fp16.
// ---------------------------------------------------------------------------
__global__ __launch_bounds__(256) void proj_mma(
    const float* __restrict__ bp, float* __restrict__ outp)
{
    extern __shared__ __half dynsm[];
    int tid = threadIdx.x, wid = tid >> 5, lane = tid & 31;
    int wm = wid >> 2, wn = wid & 3;
    const int m0 = blockIdx.x * 128, n0 = blockIdx.y * 128;

    uint32_t sbase = smem_u32(dynsm);
    uint32_t aoff = ((wm*64 + (lane & 15)) * SK + ((lane >> 4) << 3)) * 2;
    uint32_t boff = ((wn*32 + (lane & 7)) * SK + (((lane >> 3) & 1) << 3)) * 2;

    float acc[4][4][4] = {};

    auto fill = [&](int stage, int kc) {
        uint32_t st = sbase + stage*STAGE_H*2;
        int k0 = kc * 32;
        int h = k0 >> 6, dl = k0 & 63;
        #pragma unroll
        for (int it = 0; it < 4; it++) {
            int part = it >> 1;
            int idx = ((it & 1) << 8) + tid;
            int row = idx >> 2, seg = (idx & 3) << 3;
            if (part == 0) {
                int m = m0 + row, b_ = m >> 11, t = m & (T_-1);
                cp16(st + (row*SK + seg)*2,
                     g_oh + (((size_t)(b_*H_ + h))*T_ + t)*HD_ + dl + seg);
            } else {
                cp16(st + (TILE_H + row*SK + seg)*2,
                     g_wpT + (size_t)(n0 + row)*C_ + k0 + seg);
            }
        }
    };

    fill(0, 0); CP_COMMIT();
    fill(1, 1); CP_COMMIT();

    for (int kc = 0; kc < 32; kc++) {
        CP_WAIT1();
        __syncthreads();
        if (kc + 2 < 32) fill((kc + 2) % 3, kc + 2);
        CP_COMMIT();
        gemm_mma_chunk(sbase + (kc % 3)*STAGE_H*2, aoff, boff, acc);
    }

    #pragma unroll
    for (int mt = 0; mt < 4; mt++) {
        int mrow = m0 + wm*64 + mt*16 + (lane >> 2);
        #pragma unroll
        for (int half = 0; half < 2; half++) {
            int m = mrow + half*8;
            #pragma unroll
            for (int nt = 0; nt < 4; nt++) {
                int n = wn*32 + nt*8 + ((lane & 3) << 1);
                float c0 = acc[mt][nt][half*2+0] + bp[n0 + n];
                float c1 = acc[mt][nt][half*2+1] + bp[n0 + n + 1];
                *(float2*)&outp[(size_t)m*C_ + n0 + n] = make_float2(c0, c1);
            }
        }
    }
}

// ---------------------------------------------------------------------------
extern "C" void kernel_launch(void* const* d_in, const int* in_sizes, int n_in,
                              void* d_out, int out_size)
{
    const float* x  = (const float*)d_in[0];
    const float* Wq = (const float*)d_in[1];
    const float* bq = (const float*)d_in[2];
    const float* Wk = (const float*)d_in[3];
    const float* bk = (const float*)d_in[4];
    const float* Wv = (const float*)d_in[5];
    const float* bv = (const float*)d_in[6];
    const float* Wp = (const float*)d_in[7];
    const float* bp = (const float*)d_in[8];
    float* out = (float*)d_out;

    cudaFuncSetAttribute(qkv_mma,  cudaFuncAttributeMaxDynamicSharedMemorySize, GEMM_SMEM);
    cudaFuncSetAttribute(proj_mma, cudaFuncAttributeMaxDynamicSharedMemorySize, GEMM_SMEM);
    cudaFuncSetAttribute(attn_mma, cudaFuncAttributeMaxDynamicSharedMemorySize, ATTN_SMEM);

    conv_x<<<M_*C_/4/256, 256>>>(x);
    conv_w<<<4*1048576/256, 256>>>(Wq, Wk, Wv, Wp);
    stage_bias<<<4, 256>>>(bq, bk, bv);
    qkv_mma<<<dim3(64, 24), 256, GEMM_SMEM>>>();
    attn_mma<<<dim3(16, 64), 256, ATTN_SMEM>>>();
    proj_mma<<<dim3(64, 8), 256, GEMM_SMEM>>>(bp, out);
}

// round 12
// speedup vs baseline: 7.3535x; 1.1192x over previous
#include <cuda_runtime.h>
#include <cuda_fp16.h>
#include <math.h>
#include <stdint.h>

#define B_  4
#define T_  2048
#define C_  1024
#define H_  16
#define HD_ 64
#define M_  (B_*T_)   // 8192

// fp16 scratch (allocation-free)
__device__ __half g_xh[M_*C_];
__device__ __half g_wqT[H_*HD_*C_], g_wkT[H_*HD_*C_], g_wvT[H_*HD_*C_];
__device__ __half g_wpT[C_*C_];
__device__ __half g_qh[M_*C_], g_kh[M_*C_], g_vh[M_*C_];
__device__ __half g_oh[M_*C_];
__device__ float  g_bias[3*H_*HD_];

// ---------------------------------------------------------------------------
// helpers
// ---------------------------------------------------------------------------
__device__ __forceinline__ uint32_t smem_u32(const void* p){
    uint32_t a;
    asm("{ .reg .u64 t; cvta.to.shared.u64 t, %1; cvt.u32.u64 %0, t; }"
        : "=r"(a) : "l"(p));
    return a;
}
__device__ __forceinline__ void ldsm_x4(uint32_t* r, uint32_t addr){
    asm volatile("ldmatrix.sync.aligned.m8n8.x4.shared.b16 {%0,%1,%2,%3}, [%4];"
        : "=r"(r[0]), "=r"(r[1]), "=r"(r[2]), "=r"(r[3]) : "r"(addr));
}
__device__ __forceinline__ void ldsm_x4t(uint32_t* r, uint32_t addr){
    asm volatile("ldmatrix.sync.aligned.m8n8.x4.trans.shared.b16 {%0,%1,%2,%3}, [%4];"
        : "=r"(r[0]), "=r"(r[1]), "=r"(r[2]), "=r"(r[3]) : "r"(addr));
}
__device__ __forceinline__ void mma16816(float* c, const uint32_t* a, const uint32_t* b){
    asm volatile(
        "mma.sync.aligned.m16n8k16.row.col.f32.f16.f16.f32 "
        "{%0,%1,%2,%3}, {%4,%5,%6,%7}, {%8,%9}, {%0,%1,%2,%3};"
        : "+f"(c[0]), "+f"(c[1]), "+f"(c[2]), "+f"(c[3])
        : "r"(a[0]), "r"(a[1]), "r"(a[2]), "r"(a[3]), "r"(b[0]), "r"(b[1]));
}
__device__ __forceinline__ void cp16(uint32_t dst, const void* src){
    asm volatile("cp.async.cg.shared.global [%0], [%1], 16;" :: "r"(dst), "l"(src));
}
#define CP_COMMIT() asm volatile("cp.async.commit_group;" ::: "memory")
#define CP_WAIT1()  asm volatile("cp.async.wait_group 1;" ::: "memory")

__device__ __forceinline__ uint32_t pack_h(float a, float b){
    __half2 hp = __floats2half2_rn(a, b);
    return *(uint32_t*)&hp;
}

// ---------------------------------------------------------------------------
// Prologue kernels
// ---------------------------------------------------------------------------
__global__ __launch_bounds__(256) void conv_x(const float* __restrict__ x){
    int i = (blockIdx.x*256 + threadIdx.x) * 4;
    float4 a = *(const float4*)(x + i);
    uint2 hi;
    hi.x = pack_h(a.x, a.y);
    hi.y = pack_h(a.z, a.w);
    *(uint2*)&g_xh[i] = hi;
}

__global__ __launch_bounds__(256) void conv_w(
    const float* __restrict__ Wq, const float* __restrict__ Wk,
    const float* __restrict__ Wv, const float* __restrict__ Wp)
{
    int idx = blockIdx.x*256 + threadIdx.x;           // 0 .. 4M-1
    int which = idx >> 20;
    int o = idx & 0xFFFFF;
    if (which < 3) {
        const float* W = (which == 0) ? Wq : (which == 1) ? Wk : Wv;
        __half* wT = (which == 0) ? g_wqT : (which == 1) ? g_wkT : g_wvT;
        int c = o & (C_-1);
        int d = (o >> 10) & 63;
        int h = o >> 16;
        wT[o] = __float2half_rn(W[((size_t)h*C_ + c)*HD_ + d]);
    } else {
        int k = o & (C_-1);
        int n = o >> 10;
        g_wpT[o] = __float2half_rn(Wp[(size_t)k*C_ + n]);
    }
}

__global__ void stage_bias(const float* bq, const float* bk, const float* bv){
    int i = threadIdx.x + blockIdx.x*256;
    if (i < H_*HD_) {
        g_bias[i] = bq[i];
        g_bias[H_*HD_ + i] = bk[i];
        g_bias[2*H_*HD_ + i] = bv[i];
    }
}

// ---------------------------------------------------------------------------
// GEMM mma chunk: BK=64, single fp16 pass, paired-x4 B loads.
// ---------------------------------------------------------------------------
#define BK  64
#define SK  72                    // 64 halves + 8 pad
#define TILE_H (128*SK)           // 9216 halves
#define STAGE_H (2*TILE_H)        // A|B
#define GEMM_SMEM (3*STAGE_H*2)   // 110592 B

__device__ __forceinline__ void gemm_mma_chunk(
    uint32_t st, uint32_t aoff, int wn, int lane, float acc[4][4][4])
{
    uint32_t sA = st, sB = st + TILE_H*2;
    int g01 = (lane >> 4) << 3;          // (g>>1)*8
    int gk  = ((lane >> 3) & 1) << 3;    // (g&1)*8
    int l7  = lane & 7;

    #pragma unroll
    for (int ks = 0; ks < 4; ks++) {
        uint32_t bf[4][2];
        #pragma unroll
        for (int ntp = 0; ntp < 2; ntp++) {
            uint32_t tmp[4];
            uint32_t addr = sB + (((uint32_t)(wn*32 + ntp*16 + g01 + l7))*SK
                                  + ks*16 + gk)*2;
            ldsm_x4(tmp, addr);
            bf[2*ntp][0] = tmp[0]; bf[2*ntp][1] = tmp[1];
            bf[2*ntp+1][0] = tmp[2]; bf[2*ntp+1][1] = tmp[3];
        }
        uint32_t af[4][4];
        #pragma unroll
        for (int mt = 0; mt < 4; mt++)
            ldsm_x4(af[mt], sA + aoff + (mt*16*SK + ks*16)*2);
        #pragma unroll
        for (int mt = 0; mt < 4; mt++)
            #pragma unroll
            for (int nt = 0; nt < 4; nt++)
                mma16816(acc[mt][nt], af[mt], bf[nt]);
    }
}

// ---------------------------------------------------------------------------
// Kernel 1: QKV projection — BK=64, 3-stage, single-pass fp16.
// ---------------------------------------------------------------------------
__global__ __launch_bounds__(256) void qkv_mma()
{
    extern __shared__ __half dynsm[];
    int tid = threadIdx.x, wid = tid >> 5, lane = tid & 31;
    int wm = wid >> 2, wn = wid & 3;
    int mt_ = blockIdx.x, nt_ = blockIdx.y;
    int which = nt_ >> 3, hbase = (nt_ & 7) * 2;
    const int m0 = mt_ * 128;

    const __half* wT = (which == 0) ? g_wqT : (which == 1) ? g_wkT : g_wvT;
    __half* outp = (which == 0) ? g_qh : (which == 1) ? g_kh : g_vh;
    uint32_t sbase = smem_u32(dynsm);
    uint32_t aoff = ((wm*64 + (lane & 15)) * SK + ((lane >> 4) << 3)) * 2;

    float acc[4][4][4] = {};

    auto fill = [&](int stage, int kc) {
        uint32_t st = sbase + stage*STAGE_H*2;
        int k0 = kc * BK;
        #pragma unroll
        for (int it = 0; it < 8; it++) {
            int part = it >> 2;
            int idx = ((it & 3) << 8) + tid;
            int row = idx >> 3, seg = (idx & 7) << 3;
            if (part == 0) {
                cp16(st + (row*SK + seg)*2,
                     g_xh + (size_t)(m0 + row)*C_ + k0 + seg);
            } else {
                int h = hbase + (row >> 6), d = row & 63;
                cp16(st + (TILE_H + row*SK + seg)*2,
                     wT + ((size_t)h*HD_ + d)*C_ + k0 + seg);
            }
        }
    };

    fill(0, 0); CP_COMMIT();
    fill(1, 1); CP_COMMIT();

    for (int kc = 0; kc < 16; kc++) {
        CP_WAIT1();
        __syncthreads();
        if (kc + 2 < 16) fill((kc + 2) % 3, kc + 2);
        CP_COMMIT();
        gemm_mma_chunk(sbase + (kc % 3)*STAGE_H*2, aoff, wn, lane, acc);
    }

    #pragma unroll
    for (int mt = 0; mt < 4; mt++) {
        int mrow = m0 + wm*64 + mt*16 + (lane >> 2);
        #pragma unroll
        for (int half = 0; half < 2; half++) {
            int m = mrow + half*8;
            int b_ = m >> 11, t = m & (T_-1);
            #pragma unroll
            for (int nt = 0; nt < 4; nt++) {
                int n = wn*32 + nt*8 + ((lane & 3) << 1);
                int h = hbase + (n >> 6), d = n & 63;
                size_t off = (((size_t)(b_*H_ + h))*T_ + t)*HD_ + d;
                float c0 = acc[mt][nt][half*2+0] + g_bias[(which*H_ + h)*HD_ + d];
                float c1 = acc[mt][nt][half*2+1] + g_bias[(which*H_ + h)*HD_ + d + 1];
                *(uint32_t*)&outp[off] = pack_h(c0, c1);
            }
        }
    }
}

// ---------------------------------------------------------------------------
// Kernel 2: attention — single-pass, paired-x4 fragment loads.
// ---------------------------------------------------------------------------
#define SKA 72
#define ATILE_H (64*SKA)
#define ASTAGE_H (2*ATILE_H)
#define ATTN_SMEM (3*ASTAGE_H*2)   // 55296 B

__global__ __launch_bounds__(256) void attn_mma()
{
    extern __shared__ __half asm_[];
    int tid = threadIdx.x, wid = tid >> 5, lane = tid & 31;
    int qt = 15 - blockIdx.x;
    int bh = blockIdx.y;
    const __half* Qh = g_qh + (size_t)bh * T_ * HD_;
    const __half* Kh = g_kh + (size_t)bh * T_ * HD_;
    const __half* Vh = g_vh + (size_t)bh * T_ * HD_;

    uint32_t sbase = smem_u32(asm_);
    int r0 = lane >> 2, c0 = (lane & 3) << 1;
    int wrow = qt*128 + wid*16;
    int row0 = wrow + r0;
    int g01 = (lane >> 4) << 3;
    int gk  = ((lane >> 3) & 1) << 3;
    int l7  = lane & 7;

    uint32_t qh[4][4];
    #pragma unroll
    for (int ks = 0; ks < 4; ks++) {
        #pragma unroll
        for (int p = 0; p < 4; p++) {
            int rr = row0 + ((p & 1) << 3);
            int cc = ks*16 + c0 + ((p >> 1) << 3);
            qh[ks][p] = *(const uint32_t*)&Qh[(size_t)rr*HD_ + cc];
        }
    }

    float o[8][4];
    #pragma unroll
    for (int i = 0; i < 8; i++) { o[i][0]=o[i][1]=o[i][2]=o[i][3]=0.f; }
    float m_i[2] = {-1e30f, -1e30f}, l_i[2] = {0.f, 0.f};
    int jmax = 2*qt + 1;

    auto fill = [&](int stage, int j) {
        uint32_t st = sbase + stage*ASTAGE_H*2;
        int s0 = j * 64;
        #pragma unroll
        for (int it = 0; it < 4; it++) {
            int part = it >> 1;
            int idx = ((it & 1) << 8) + tid;
            int row = idx >> 3, seg = (idx & 7) << 3;
            if (part == 0)
                cp16(st + (row*SKA + seg)*2, Kh + (size_t)(s0 + row)*HD_ + seg);
            else
                cp16(st + (ATILE_H + row*SKA + seg)*2, Vh + (size_t)(s0 + row)*HD_ + seg);
        }
    };

    fill(0, 0); CP_COMMIT();
    fill(1, 1); CP_COMMIT();

    for (int j = 0; j <= jmax; j++) {
        CP_WAIT1();
        __syncthreads();
        if (j + 2 <= jmax) fill((j + 2) % 3, j + 2);
        CP_COMMIT();

        bool dead = (j*64) > (wrow + 15);
        if (!dead) {
            uint32_t st = sbase + (j % 3)*ASTAGE_H*2;
            uint32_t sK = st, sV = st + ATILE_H*2;
            // S = Q K^T (single pass, paired-x4 K loads)
            float c[8][4] = {};
            #pragma unroll
            for (int ks = 0; ks < 4; ks++) {
                uint32_t bf[8][2];
                #pragma unroll
                for (int ntp = 0; ntp < 4; ntp++) {
                    uint32_t tmp[4];
                    uint32_t addr = sK + (((uint32_t)(ntp*16 + g01 + l7))*SKA
                                          + ks*16 + gk)*2;
                    ldsm_x4(tmp, addr);
                    bf[2*ntp][0] = tmp[0]; bf[2*ntp][1] = tmp[1];
                    bf[2*ntp+1][0] = tmp[2]; bf[2*ntp+1][1] = tmp[3];
                }
                #pragma unroll
                for (int nt = 0; nt < 8; nt++)
                    mma16816(c[nt], qh[ks], bf[nt]);
            }
            // scale + causal mask
            bool dflag = (j >= 2*qt);
            #pragma unroll
            for (int nt = 0; nt < 8; nt++) {
                #pragma unroll
                for (int e = 0; e < 4; e++) {
                    float s = c[nt][e] * 0.03125f;
                    if (dflag) {
                        int col = j*64 + nt*8 + c0 + (e & 1);
                        int row = row0 + ((e >> 1) << 3);
                        if (col > row) s = -1e30f;
                    }
                    c[nt][e] = s;
                }
            }
            // online softmax
            #pragma unroll
            for (int r = 0; r < 2; r++) {
                float mx = -1e30f;
                #pragma unroll
                for (int nt = 0; nt < 8; nt++)
                    mx = fmaxf(mx, fmaxf(c[nt][2*r], c[nt][2*r+1]));
                mx = fmaxf(mx, __shfl_xor_sync(0xffffffffu, mx, 1));
                mx = fmaxf(mx, __shfl_xor_sync(0xffffffffu, mx, 2));
                float mnew = fmaxf(m_i[r], mx);
                float alpha = __expf(m_i[r] - mnew);
                m_i[r] = mnew;
                float rs = 0.f;
                #pragma unroll
                for (int nt = 0; nt < 8; nt++) {
                    float p0 = __expf(c[nt][2*r]   - mnew);
                    float p1 = __expf(c[nt][2*r+1] - mnew);
                    c[nt][2*r] = p0; c[nt][2*r+1] = p1;
                    rs += p0 + p1;
                }
                rs += __shfl_xor_sync(0xffffffffu, rs, 1);
                rs += __shfl_xor_sync(0xffffffffu, rs, 2);
                l_i[r] = l_i[r]*alpha + rs;
                #pragma unroll
                for (int nt = 0; nt < 8; nt++) {
                    o[nt][2*r]   *= alpha;
                    o[nt][2*r+1] *= alpha;
                }
            }
            // O += P V (single pass, paired-x4 trans V loads)
            #pragma unroll
            for (int ks = 0; ks < 4; ks++) {
                uint32_t ph[4];
                ph[0] = pack_h(c[2*ks][0],   c[2*ks][1]);
                ph[1] = pack_h(c[2*ks][2],   c[2*ks][3]);
                ph[2] = pack_h(c[2*ks+1][0], c[2*ks+1][1]);
                ph[3] = pack_h(c[2*ks+1][2], c[2*ks+1][3]);
                uint32_t bv[8][2];
                #pragma unroll
                for (int ntp = 0; ntp < 4; ntp++) {
                    uint32_t tmp[4];
                    uint32_t addr = sV + (((uint32_t)(ks*16 + gk + l7))*SKA
                                          + ntp*16 + g01)*2;
                    ldsm_x4t(tmp, addr);
                    bv[2*ntp][0] = tmp[0]; bv[2*ntp][1] = tmp[1];
                    bv[2*ntp+1][0] = tmp[2]; bv[2*ntp+1][1] = tmp[3];
                }
                #pragma unroll
                for (int nt = 0; nt < 8; nt++)
                    mma16816(o[nt], ph, bv[nt]);
            }
        }
        __syncthreads();
    }

    float inv0 = 1.0f / l_i[0], inv1 = 1.0f / l_i[1];
    __half* Oh = g_oh + (size_t)bh * T_ * HD_;
    #pragma unroll
    for (int nt = 0; nt < 8; nt++) {
        int d = nt*8 + c0;
        *(uint32_t*)&Oh[(size_t)row0*HD_ + d]     = pack_h(o[nt][0]*inv0, o[nt][1]*inv0);
        *(uint32_t*)&Oh[(size_t)(row0+8)*HD_ + d] = pack_h(o[nt][2]*inv1, o[nt][3]*inv1);
    }
}

// ---------------------------------------------------------------------------
// Kernel 3: output projection — BK=64, 3-stage, single-pass fp16.
// ---------------------------------------------------------------------------
__global__ __launch_bounds__(256) void proj_mma(
    const float* __restrict__ bp, float* __restrict__ outp)
{
    extern __shared__ __half dynsm[];
    int tid = threadIdx.x, wid = tid >> 5, lane = tid & 31;
    int wm = wid >> 2, wn = wid & 3;
    const int m0 = blockIdx.x * 128, n0 = blockIdx.y * 128;

    uint32_t sbase = smem_u32(dynsm);
    uint32_t aoff = ((wm*64 + (lane & 15)) * SK + ((lane >> 4) << 3)) * 2;

    float acc[4][4][4] = {};

    auto fill = [&](int stage, int kc) {
        uint32_t st = sbase + stage*STAGE_H*2;
        int k0 = kc * BK;
        int h = k0 >> 6;      // BK=64 aligns with head boundary
        #pragma unroll
        for (int it = 0; it < 8; it++) {
            int part = it >> 2;
            int idx = ((it & 3) << 8) + tid;
            int row = idx >> 3, seg = (idx & 7) << 3;
            if (part == 0) {
                int m = m0 + row, b_ = m >> 11, t = m & (T_-1);
                cp16(st + (row*SK + seg)*2,
                     g_oh + (((size_t)(b_*H_ + h))*T_ + t)*HD_ + seg);
            } else {
                cp16(st + (TILE_H + row*SK + seg)*2,
                     g_wpT + (size_t)(n0 + row)*C_ + k0 + seg);
            }
        }
    };

    fill(0, 0); CP_COMMIT();
    fill(1, 1); CP_COMMIT();

    for (int kc = 0; kc < 16; kc++) {
        CP_WAIT1();
        __syncthreads();
        if (kc + 2 < 16) fill((kc + 2) % 3, kc + 2);
        CP_COMMIT();
        gemm_mma_chunk(sbase + (kc % 3)*STAGE_H*2, aoff, wn, lane, acc);
    }

    #pragma unroll
    for (int mt = 0; mt < 4; mt++) {
        int mrow = m0 + wm*64 + mt*16 + (lane >> 2);
        #pragma unroll
        for (int half = 0; half < 2; half++) {
            int m = mrow + half*8;
            #pragma unroll
            for (int nt = 0; nt < 4; nt++) {
                int n = wn*32 + nt*8 + ((lane & 3) << 1);
                float c0 = acc[mt][nt][half*2+0] + bp[n0 + n];
                float c1 = acc[mt][nt][half*2+1] + bp[n0 + n + 1];
                *(float2*)&outp[(size_t)m*C_ + n0 + n] = make_float2(c0, c1);
            }
        }
    }
}

// ---------------------------------------------------------------------------
extern "C" void kernel_launch(void* const* d_in, const int* in_sizes, int n_in,
                              void* d_out, int out_size)
{
    const float* x  = (const float*)d_in[0];
    const float* Wq = (const float*)d_in[1];
    const float* bq = (const float*)d_in[2];
    const float* Wk = (const float*)d_in[3];
    const float* bk = (const float*)d_in[4];
    const float* Wv = (const float*)d_in[5];
    const float* bv = (const float*)d_in[6];
    const float* Wp = (const float*)d_in[7];
    const float* bp = (const float*)d_in[8];
    float* out = (float*)d_out;

    cudaFuncSetAttribute(qkv_mma,  cudaFuncAttributeMaxDynamicSharedMemorySize, GEMM_SMEM);
    cudaFuncSetAttribute(proj_mma, cudaFuncAttributeMaxDynamicSharedMemorySize, GEMM_SMEM);
    cudaFuncSetAttribute(attn_mma, cudaFuncAttributeMaxDynamicSharedMemorySize, ATTN_SMEM);

    conv_x<<<M_*C_/4/256, 256>>>(x);
    conv_w<<<4*1048576/256, 256>>>(Wq, Wk, Wv, Wp);
    stage_bias<<<4, 256>>>(bq, bk, bv);
    qkv_mma<<<dim3(64, 24), 256, GEMM_SMEM>>>();
    attn_mma<<<dim3(16, 64), 256, ATTN_SMEM>>>();
    proj_mma<<<dim3(64, 8), 256, GEMM_SMEM>>>(bp, out);
}